// round 15
// baseline (speedup 1.0000x reference)
#include <cuda_runtime.h>
#include <cuda_bf16.h>
#include <math.h>
#include <stdint.h>

#define NTOK 131072
#define EMBD 128
#define XYH  4096
#define HID  512
#define NB_RED 256
#define ROWS_PER_RED (NTOK / NB_RED)   // 512
#define SCALE_F 11.313708498984761f    // sqrt(128)
#define GSMEM (3 * 128 * 136 * 2 + 2 * 256 * 4)   // As + Bs0 + Bs1 + stats = 106496
// ffn M=64: As(64x136) + Hs(64x136) + B0(128x136) + B1(128x136) + stats = 106496
#define FSMEM (2 * 64 * 136 * 2 + 2 * 128 * 136 * 2 + 2 * 256 * 4)

// ---------------- scratch (device globals; no allocation allowed) ------------
__device__ float g_x[NTOK * EMBD];              // residual stream [N, E] fp32
__device__ __nv_bfloat16 g_qkv[NTOK * 384];     // qkv HEAD-MAJOR: [xy][z][384]
__device__ __nv_bfloat16 g_att[NTOK * EMBD];    // attention output, bf16 [N, E]
__device__ float g_part[2048 * 256];            // per-CTA partial sums / sumsq
__device__ float g_part2[16 * 256];             // stage-2 partials
__device__ float g_scale[EMBD];                 // folded norm scale per channel
__device__ float g_shift[EMBD];                 // folded norm shift per channel
// pre-converted bf16 weights
__device__ __nv_bfloat16 g_wqkv_b[3 * 128 * 384];   // permuted [q|k|v] planes
__device__ __nv_bfloat16 g_wp_b[3 * 128 * 128];
__device__ __nv_bfloat16 g_w1_b[3 * 128 * 512];
__device__ __nv_bfloat16 g_w2_b[3 * 512 * 128];
__device__ float g_bp[3 * 384];                 // permuted bqkv (fp32)

// ---------------- PTX helpers --------------------------------------------------
__device__ __forceinline__ void mma_bf16(float* d, uint32_t a0, uint32_t a1,
                                         uint32_t a2, uint32_t a3,
                                         uint32_t b0, uint32_t b1) {
    asm volatile(
        "mma.sync.aligned.m16n8k16.row.col.f32.bf16.bf16.f32 "
        "{%0,%1,%2,%3}, {%4,%5,%6,%7}, {%8,%9}, {%0,%1,%2,%3};\n"
        : "+f"(d[0]), "+f"(d[1]), "+f"(d[2]), "+f"(d[3])
        : "r"(a0), "r"(a1), "r"(a2), "r"(a3), "r"(b0), "r"(b1));
}

__device__ __forceinline__ void ldsm_x4(uint32_t* r, const void* p) {
    uint32_t addr = (uint32_t)__cvta_generic_to_shared(p);
    asm volatile("ldmatrix.sync.aligned.m8n8.x4.shared.b16 {%0,%1,%2,%3}, [%4];"
                 : "=r"(r[0]), "=r"(r[1]), "=r"(r[2]), "=r"(r[3]) : "r"(addr));
}

__device__ __forceinline__ void ldsm_x4_t(uint32_t* r, const void* p) {
    uint32_t addr = (uint32_t)__cvta_generic_to_shared(p);
    asm volatile("ldmatrix.sync.aligned.m8n8.x4.trans.shared.b16 {%0,%1,%2,%3}, [%4];"
                 : "=r"(r[0]), "=r"(r[1]), "=r"(r[2]), "=r"(r[3]) : "r"(addr));
}

__device__ __forceinline__ void cp16(void* smem, const void* gmem) {
    uint32_t s = (uint32_t)__cvta_generic_to_shared(smem);
    asm volatile("cp.async.ca.shared.global [%0], [%1], 16;" :: "r"(s), "l"(gmem));
}

__device__ __forceinline__ void cp_commit() {
    asm volatile("cp.async.commit_group;" ::: "memory");
}

__device__ __forceinline__ void cp_wait0() {
    asm volatile("cp.async.wait_group 0;" ::: "memory");
}

__device__ __forceinline__ void cp_wait_all() {
    asm volatile("cp.async.commit_group;\ncp.async.wait_group 0;" ::: "memory");
}

__device__ __forceinline__ __nv_bfloat162 cvt2(float x, float y) {
    return __nv_bfloat162(__float2bfloat16_rn(x), __float2bfloat16_rn(y));
}

// ---------------- transpose in: img [E, N] -> x [N, E] -----------------------
__global__ void t_in_kernel(const float* __restrict__ img, float* __restrict__ x) {
    __shared__ float tile[32][33];
    int n0 = blockIdx.x * 32, m0 = blockIdx.y * 32;
    #pragma unroll
    for (int r = threadIdx.y; r < 32; r += 8)
        tile[r][threadIdx.x] = img[(size_t)(m0 + r) * NTOK + n0 + threadIdx.x];
    __syncthreads();
    #pragma unroll
    for (int r = threadIdx.y; r < 32; r += 8)
        x[(size_t)(n0 + r) * EMBD + m0 + threadIdx.x] = tile[threadIdx.x][r];
}

// ---------------- one-time weight prep: permute Wqkv, cvt all weights bf16 ----
__global__ void prep_w_kernel(const float* __restrict__ Wqkv, const float* __restrict__ bqkv,
                              const float* __restrict__ Wp, const float* __restrict__ W1,
                              const float* __restrict__ W2) {
    int idx = blockIdx.x * 256 + threadIdx.x;
    if (idx < 147456) {
        int l = idx / 49152, rem = idx % 49152;
        int k = rem / 384, cc = rem % 384;
        g_wqkv_b[l * 49152 + k * 384 + (cc % 3) * 128 + cc / 3] =
            __float2bfloat16_rn(Wqkv[idx]);
    } else if (idx < 196608) {
        int j = idx - 147456;
        g_wp_b[j] = __float2bfloat16_rn(Wp[j]);
    } else if (idx < 393216) {
        int j = idx - 196608;
        g_w1_b[j] = __float2bfloat16_rn(W1[j]);
    } else if (idx < 589824) {
        int j = idx - 393216;
        g_w2_b[j] = __float2bfloat16_rn(W2[j]);
    }
    if (idx < 3 * 384) {
        int l = idx / 384, cc = idx % 384;
        g_bp[l * 384 + (cc % 3) * 128 + cc / 3] = bqkv[idx];
    }
}

// ---------------- instance norm: stage 1 (only for the very first norm) -------
__global__ void reduce_kernel(const float* __restrict__ x) {
    int b = blockIdx.x;
    int c = threadIdx.x;
    float s = 0.f, ss = 0.f;
    int r0 = b * ROWS_PER_RED;
    for (int r = 0; r < ROWS_PER_RED; r++) {
        float v = x[(size_t)(r0 + r) * EMBD + c];
        s += v;
        ss += v * v;
    }
    g_part[b * 256 + c] = s;
    g_part[b * 256 + 128 + c] = ss;
}

// ---------------- norm fold stage A: NP partials -> 16 partials ---------------
template <int NP>
__global__ void fold_kernel() {
    int b = blockIdx.x;        // 16
    int c = threadIdx.x;       // 256
    const int SEG = NP / 16;
    float s = 0.f;
    for (int r = 0; r < SEG; r++) s += g_part[(size_t)(b * SEG + r) * 256 + c];
    g_part2[b * 256 + c] = s;
}

// ---------------- norm fold stage B: 16 partials -> scale/shift ---------------
__global__ void finalize16(const float* __restrict__ g, const float* __restrict__ b) {
    __shared__ float sh[256];
    int t = threadIdx.x;       // 256
    float s = 0.f;
    #pragma unroll
    for (int r = 0; r < 16; r++) s += g_part2[r * 256 + t];
    sh[t] = s;
    __syncthreads();
    if (t < 128) {
        float su = sh[t], ss = sh[t + 128];
        float mean = su * (1.0f / NTOK);
        float var = ss * (1.0f / NTOK) - mean * mean;
        float sc = rsqrtf(var + 1e-5f) * g[t];
        g_scale[t] = sc;
        g_shift[t] = b[t] - mean * sc;
    }
}

// ---------------- bf16 tensor-core GEMM (qkv / proj), pipelined N-tile loop ----
// PERM: write bf16 output rows head-major: wrow = (t & 4095)*32 + (t >> 12)
template <int K, int NC, bool NORM, bool HSWISH, bool RES, bool ABF16, bool OBF16,
          bool STATS, bool PERM>
__global__ __launch_bounds__(256, 2) void gemm_kernel(const void* __restrict__ Av,
                                                      const __nv_bfloat16* __restrict__ W,
                                                      const float* __restrict__ bias,
                                                      void* __restrict__ Cv) {
    constexpr int NT = NC / 128;
    static_assert(K == 128, "K=128 only");

    extern __shared__ char sm_raw[];
    typedef __nv_bfloat16 bfrow[136];
    bfrow* As  = (bfrow*)sm_raw;
    bfrow* Bs0 = (bfrow*)(sm_raw + 34816);
    bfrow* Bs1 = (bfrow*)(sm_raw + 2 * 34816);
    float* s_sum = (float*)(sm_raw + 3 * 34816);
    float* s_ss  = s_sum + 256;

    int tid = threadIdx.x;
    int m0 = blockIdx.y * 128;
    int lane = tid & 31, wid = tid >> 5;
    int wm0 = (wid & 1) * 64;
    int wn0 = (wid >> 1) * 32;
    int g = lane >> 2, c = lane & 3;

    float csum[8] = {}, css[8] = {};

    int a_r = lane & 15, a_c = (lane >> 4) * 8;
    int b_r = (lane & 7) + ((lane >> 3) & 1) * 8, b_c = (lane >> 4) * 8;

    int cprow = tid >> 4, cpcol = (tid & 15) * 8;

    // prefetch B tile 0
    #pragma unroll
    for (int r = 0; r < 8; r++) {
        int rr = cprow + 16 * r;
        cp16(&Bs0[rr][cpcol], &W[(size_t)rr * NC + cpcol]);
    }
    cp_commit();

    // ---- load A tile 128x128 ONCE (overlaps B prefetch)
    if (ABF16) {
        const __nv_bfloat16* A = (const __nv_bfloat16*)Av;
        #pragma unroll
        for (int r = 0; r < 8; r++) {
            int rr = cprow + 16 * r;
            cp16(&As[rr][cpcol], &A[(size_t)(m0 + rr) * 128 + cpcol]);
        }
        cp_commit();
    } else {
        const float* A = (const float*)Av;
        int row0 = tid >> 3, colb = (tid & 7) * 4;
        #pragma unroll
        for (int r = 0; r < 4; r++) {
            int rr = row0 + 32 * r;
            #pragma unroll
            for (int cb = 0; cb < 4; cb++) {
                int col = colb + 32 * cb;
                float4 v = *(const float4*)&A[(size_t)(m0 + rr) * 128 + col];
                if (NORM) {
                    float4 sc = *(const float4*)&g_scale[col];
                    float4 sh = *(const float4*)&g_shift[col];
                    v.x = fmaf(v.x, sc.x, sh.x);
                    v.y = fmaf(v.y, sc.y, sh.y);
                    v.z = fmaf(v.z, sc.z, sh.z);
                    v.w = fmaf(v.w, sc.w, sh.w);
                }
                *(__nv_bfloat162*)&As[rr][col] = cvt2(v.x, v.y);
                *(__nv_bfloat162*)&As[rr][col + 2] = cvt2(v.z, v.w);
            }
        }
    }

    #pragma unroll
    for (int nt = 0; nt < NT; nt++) {
        cp_wait0();
        __syncthreads();
        bfrow* Bc = (nt & 1) ? Bs1 : Bs0;
        if (nt + 1 < NT) {
            bfrow* Bn = (nt & 1) ? Bs0 : Bs1;
            #pragma unroll
            for (int r = 0; r < 8; r++) {
                int rr = cprow + 16 * r;
                cp16(&Bn[rr][cpcol], &W[(size_t)rr * NC + (nt + 1) * 128 + cpcol]);
            }
            cp_commit();
        }

        float acc[4][4][4] = {};
        #pragma unroll
        for (int ks = 0; ks < 128; ks += 16) {
            uint32_t bfr[2][4];
            ldsm_x4_t(bfr[0], &Bc[ks + b_r][wn0 + b_c]);
            ldsm_x4_t(bfr[1], &Bc[ks + b_r][wn0 + 16 + b_c]);
            #pragma unroll
            for (int i = 0; i < 4; i++) {
                uint32_t afr[4];
                ldsm_x4(afr, &As[wm0 + 16 * i + a_r][ks + a_c]);
                #pragma unroll
                for (int j = 0; j < 4; j++)
                    mma_bf16(acc[i][j], afr[0], afr[1], afr[2], afr[3],
                             bfr[j >> 1][(j & 1) * 2], bfr[j >> 1][(j & 1) * 2 + 1]);
            }
        }
        // epilogue
        #pragma unroll
        for (int i = 0; i < 4; i++) {
            #pragma unroll
            for (int h = 0; h < 2; h++) {
                int row = m0 + wm0 + 16 * i + g + 8 * h;
                int wrow = PERM ? ((row & (XYH - 1)) * 32 + (row >> 12)) : row;
                #pragma unroll
                for (int j = 0; j < 4; j++) {
                    int col = nt * 128 + wn0 + 8 * j + 2 * c;
                    float2 bv = *(const float2*)&bias[col];
                    float x0 = acc[i][j][2 * h + 0] + bv.x;
                    float x1 = acc[i][j][2 * h + 1] + bv.y;
                    if (HSWISH) {
                        x0 = x0 * fminf(fmaxf(x0 + 3.f, 0.f), 6.f) * (1.f / 6.f);
                        x1 = x1 * fminf(fmaxf(x1 + 3.f, 0.f), 6.f) * (1.f / 6.f);
                    }
                    if (OBF16) {
                        __nv_bfloat16* Cb = (__nv_bfloat16*)Cv;
                        *(__nv_bfloat162*)&Cb[(size_t)wrow * NC + col] = cvt2(x0, x1);
                    } else {
                        float2* cp = (float2*)&((float*)Cv)[(size_t)row * NC + col];
                        if (RES) {
                            float2 rr = *cp;
                            x0 += rr.x; x1 += rr.y;
                        }
                        *cp = make_float2(x0, x1);
                        if (STATS) {
                            csum[2 * j]     += x0;  css[2 * j]     += x0 * x0;
                            csum[2 * j + 1] += x1;  css[2 * j + 1] += x1 * x1;
                        }
                    }
                }
            }
        }
    }

    if (STATS) {
        #pragma unroll
        for (int k = 0; k < 8; k++) {
            #pragma unroll
            for (int off = 4; off < 32; off <<= 1) {
                csum[k] += __shfl_xor_sync(0xffffffffu, csum[k], off);
                css[k]  += __shfl_xor_sync(0xffffffffu, css[k], off);
            }
        }
        __syncthreads();
        if (lane < 4) {
            #pragma unroll
            for (int j = 0; j < 4; j++) {
                int col = wn0 + 8 * j + 2 * lane;
                s_sum[(wid & 1) * 128 + col]     = csum[2 * j];
                s_sum[(wid & 1) * 128 + col + 1] = csum[2 * j + 1];
                s_ss[(wid & 1) * 128 + col]      = css[2 * j];
                s_ss[(wid & 1) * 128 + col + 1]  = css[2 * j + 1];
            }
        }
        __syncthreads();
        if (tid < 128) {
            g_part[blockIdx.y * 256 + tid]       = s_sum[tid] + s_sum[128 + tid];
            g_part[blockIdx.y * 256 + 128 + tid] = s_ss[tid] + s_ss[128 + tid];
        }
    }
}

// ---------------- fused FFN, M=64 tile, 2 CTAs/SM ------------------------------
// h = hswish(norm(x)W1+b1); x += hW2+b2
// LAST=false: writes px + norm1 stats. LAST=true: relu + transpose -> out [E,N].
template <bool LAST>
__global__ __launch_bounds__(256, 2) void ffn_kernel(const float* __restrict__ px_in,
                                                     const __nv_bfloat16* __restrict__ W1,
                                                     const float* __restrict__ b1,
                                                     const __nv_bfloat16* __restrict__ W2,
                                                     const float* __restrict__ b2,
                                                     float* __restrict__ px_out,
                                                     float* __restrict__ outp) {
    extern __shared__ char sm_raw[];
    typedef __nv_bfloat16 bfrow[136];
    bfrow* As = (bfrow*)sm_raw;                 // [64][136]
    bfrow* Hs = (bfrow*)(sm_raw + 17408);       // [64][136]
    bfrow* B0 = (bfrow*)(sm_raw + 34816);       // [128][136] W1 tiles
    bfrow* B1 = (bfrow*)(sm_raw + 69632);       // [128][136] W2 chunks
    float* s_sum = (float*)(sm_raw + 104448);   // [2*128]
    float* s_ss  = s_sum + 256;
    float* T = (float*)sm_raw;                  // LAST: [128][68] transpose staging

    int tid = threadIdx.x;
    int m0 = blockIdx.y * 64;
    int lane = tid & 31, wid = tid >> 5;
    int wm0 = (wid & 1) * 32;                   // m half of 32
    int wn0 = (wid >> 1) * 32;                  // n quarter of 32
    int g = lane >> 2, c = lane & 3;

    int a_r = lane & 15, a_c = (lane >> 4) * 8;
    int b_r = (lane & 7) + ((lane >> 3) & 1) * 8, b_c = (lane >> 4) * 8;
    int cprow = tid >> 4, cpcol = (tid & 15) * 8;

    // prefetch W1 tile 0 (128x128)
    #pragma unroll
    for (int r = 0; r < 8; r++) {
        int rr = cprow + 16 * r;
        cp16(&B0[rr][cpcol], &W1[(size_t)rr * HID + cpcol]);
    }
    cp_commit();

    // load A tile 64x128 (fp32 + norm -> bf16): row = tid>>2, 32-col quarter
    {
        int row = tid >> 2, colq = (tid & 3) * 32;
        #pragma unroll
        for (int q = 0; q < 8; q++) {
            int col = colq + q * 4;
            float4 v = *(const float4*)&px_in[(size_t)(m0 + row) * 128 + col];
            float4 sc = *(const float4*)&g_scale[col];
            float4 sh = *(const float4*)&g_shift[col];
            v.x = fmaf(v.x, sc.x, sh.x);
            v.y = fmaf(v.y, sc.y, sh.y);
            v.z = fmaf(v.z, sc.z, sh.z);
            v.w = fmaf(v.w, sc.w, sh.w);
            *(__nv_bfloat162*)&As[row][col] = cvt2(v.x, v.y);
            *(__nv_bfloat162*)&As[row][col + 2] = cvt2(v.z, v.w);
        }
    }

    float acc2[2][4][4] = {};   // persistent ffn2 accumulator (m32 x n32 warp tile)

    #pragma unroll
    for (int nt = 0; nt < 4; nt++) {
        cp_wait_all();          // B0 = W1[nt] ready (and prior B1 consumed)
        __syncthreads();
        // async: W2 chunk nt -> B1 (hidden behind GEMM1)
        #pragma unroll
        for (int r = 0; r < 8; r++) {
            int rr = cprow + 16 * r;
            cp16(&B1[rr][cpcol], &W2[(size_t)(nt * 128 + rr) * 128 + cpcol]);
        }
        cp_commit();

        // GEMM1: acc1 = As x W1[nt]
        float acc1[2][4][4] = {};
        #pragma unroll
        for (int ks = 0; ks < 128; ks += 16) {
            uint32_t bfr[2][4];
            ldsm_x4_t(bfr[0], &B0[ks + b_r][wn0 + b_c]);
            ldsm_x4_t(bfr[1], &B0[ks + b_r][wn0 + 16 + b_c]);
            #pragma unroll
            for (int i = 0; i < 2; i++) {
                uint32_t afr[4];
                ldsm_x4(afr, &As[wm0 + 16 * i + a_r][ks + a_c]);
                #pragma unroll
                for (int j = 0; j < 4; j++)
                    mma_bf16(acc1[i][j], afr[0], afr[1], afr[2], afr[3],
                             bfr[j >> 1][(j & 1) * 2], bfr[j >> 1][(j & 1) * 2 + 1]);
            }
        }
        // bias + hswish -> Hs (bf16)
        #pragma unroll
        for (int i = 0; i < 2; i++) {
            #pragma unroll
            for (int h = 0; h < 2; h++) {
                int row = wm0 + 16 * i + g + 8 * h;
                #pragma unroll
                for (int j = 0; j < 4; j++) {
                    int col = wn0 + 8 * j + 2 * c;
                    float2 bv = *(const float2*)&b1[nt * 128 + col];
                    float x0 = acc1[i][j][2 * h + 0] + bv.x;
                    float x1 = acc1[i][j][2 * h + 1] + bv.y;
                    x0 = x0 * fminf(fmaxf(x0 + 3.f, 0.f), 6.f) * (1.f / 6.f);
                    x1 = x1 * fminf(fmaxf(x1 + 3.f, 0.f), 6.f) * (1.f / 6.f);
                    *(__nv_bfloat162*)&Hs[row][col] = cvt2(x0, x1);
                }
            }
        }
        cp_wait_all();          // B1 = W2[nt] ready
        __syncthreads();        // Hs visible; GEMM1 reads of B0 done

        // async: W1 tile nt+1 -> B0 (hidden behind GEMM2)
        if (nt < 3) {
            #pragma unroll
            for (int r = 0; r < 8; r++) {
                int rr = cprow + 16 * r;
                cp16(&B0[rr][cpcol], &W1[(size_t)rr * HID + (nt + 1) * 128 + cpcol]);
            }
            cp_commit();
        }

        // GEMM2: acc2 += Hs x W2[nt]
        #pragma unroll
        for (int ks = 0; ks < 128; ks += 16) {
            uint32_t bfr[2][4];
            ldsm_x4_t(bfr[0], &B1[ks + b_r][wn0 + b_c]);
            ldsm_x4_t(bfr[1], &B1[ks + b_r][wn0 + 16 + b_c]);
            #pragma unroll
            for (int i = 0; i < 2; i++) {
                uint32_t afr[4];
                ldsm_x4(afr, &Hs[wm0 + 16 * i + a_r][ks + a_c]);
                #pragma unroll
                for (int j = 0; j < 4; j++)
                    mma_bf16(acc2[i][j], afr[0], afr[1], afr[2], afr[3],
                             bfr[j >> 1][(j & 1) * 2], bfr[j >> 1][(j & 1) * 2 + 1]);
            }
        }
        if (nt < 3) __syncthreads();   // B1/Hs reads done before next-iter writes
    }

    if (!LAST) {
        // epilogue: + b2 + residual -> px; stats
        float csum[8] = {}, css[8] = {};
        #pragma unroll
        for (int i = 0; i < 2; i++) {
            #pragma unroll
            for (int h = 0; h < 2; h++) {
                int row = m0 + wm0 + 16 * i + g + 8 * h;
                #pragma unroll
                for (int j = 0; j < 4; j++) {
                    int col = wn0 + 8 * j + 2 * c;
                    float2 bv = *(const float2*)&b2[col];
                    float2* cp = (float2*)&px_out[(size_t)row * 128 + col];
                    float2 rr = *cp;
                    float x0 = acc2[i][j][2 * h + 0] + bv.x + rr.x;
                    float x1 = acc2[i][j][2 * h + 1] + bv.y + rr.y;
                    *cp = make_float2(x0, x1);
                    csum[2 * j]     += x0;  css[2 * j]     += x0 * x0;
                    csum[2 * j + 1] += x1;  css[2 * j + 1] += x1 * x1;
                }
            }
        }
        #pragma unroll
        for (int k = 0; k < 8; k++) {
            #pragma unroll
            for (int off = 4; off < 32; off <<= 1) {
                csum[k] += __shfl_xor_sync(0xffffffffu, csum[k], off);
                css[k]  += __shfl_xor_sync(0xffffffffu, css[k], off);
            }
        }
        __syncthreads();
        if (lane < 4) {
            #pragma unroll
            for (int j = 0; j < 4; j++) {
                int col = wn0 + 8 * j + 2 * lane;
                s_sum[(wid & 1) * 128 + col]     = csum[2 * j];
                s_sum[(wid & 1) * 128 + col + 1] = csum[2 * j + 1];
                s_ss[(wid & 1) * 128 + col]      = css[2 * j];
                s_ss[(wid & 1) * 128 + col + 1]  = css[2 * j + 1];
            }
        }
        __syncthreads();
        if (tid < 128) {
            g_part[blockIdx.y * 256 + tid]       = s_sum[tid] + s_sum[128 + tid];
            g_part[blockIdx.y * 256 + 128 + tid] = s_ss[tid] + s_ss[128 + tid];
        }
    } else {
        // LAST: relu(x) transposed -> out [E, N] via smem staging (T[128][68])
        __syncthreads();   // all GEMM2 smem reads done before reusing sm_raw as T
        #pragma unroll
        for (int i = 0; i < 2; i++) {
            #pragma unroll
            for (int h = 0; h < 2; h++) {
                int tok = wm0 + 16 * i + g + 8 * h;           // local token 0..63
                #pragma unroll
                for (int j = 0; j < 4; j++) {
                    int ch = wn0 + 8 * j + 2 * c;
                    float2 bv = *(const float2*)&b2[ch];
                    float2 rr = *(const float2*)&px_in[(size_t)(m0 + tok) * 128 + ch];
                    float x0 = acc2[i][j][2 * h + 0] + bv.x + rr.x;
                    float x1 = acc2[i][j][2 * h + 1] + bv.y + rr.y;
                    T[(ch + 0) * 68 + tok] = fmaxf(x0, 0.f);
                    T[(ch + 1) * 68 + tok] = fmaxf(x1, 0.f);
                }
            }
        }
        __syncthreads();
        int ch = tid >> 1, half = tid & 1;
        const float* Trow = &T[ch * 68 + half * 32];
        float* orow = &outp[(size_t)ch * NTOK + m0 + half * 32];
        #pragma unroll
        for (int q = 0; q < 8; q++)
            *(float4*)&orow[q * 4] = *(const float4*)&Trow[q * 4];
    }
}

// ---------------- attention: one block per head, head-major contiguous qkv ----
__global__ __launch_bounds__(128) void attn_kernel(const __nv_bfloat16* __restrict__ qkv,
                                                   __nv_bfloat16* __restrict__ out) {
    __shared__ __nv_bfloat16 qs[32][136];
    __shared__ __nv_bfloat16 kk[32][136];
    __shared__ __nv_bfloat16 vv[32][136];
    __shared__ float es[32][33];
    __shared__ __nv_bfloat16 as_[32][40];

    int xy = blockIdx.x;
    int tid = threadIdx.x;
    int lane = tid & 31, w = tid >> 5;
    int g = lane >> 2, c = lane & 3;

    // contiguous 24KB block per head: qkv[(xy*32 + z)*384 + c]
    const uint4* src = (const uint4*)(qkv + (size_t)xy * 32 * 384);
    #pragma unroll
    for (int it = 0; it < 12; it++) {
        int idx = tid + 128 * it;          // 0..1535 uint4 chunks
        uint4 v = src[idx];
        int row = idx / 48, seg = idx % 48;
        int which = seg >> 4, colh = (seg & 15) * 8;
        if (which == 0)      *(uint4*)&qs[row][colh] = v;
        else if (which == 1) *(uint4*)&kk[row][colh] = v;
        else                 *(uint4*)&vv[row][colh] = v;
    }
    __syncthreads();

    int a_r = lane & 15, a_c = (lane >> 4) * 8;
    int b_r = (lane & 7) + ((lane >> 3) & 1) * 8, b_c = (lane >> 4) * 8;

    {
        int me = 16 * (w & 1), ne = 16 * (w >> 1);
        float acc[2][4] = {};
        #pragma unroll
        for (int k0 = 0; k0 < 128; k0 += 16) {
            uint32_t afr[4], bfr[4];
            ldsm_x4(afr, &qs[me + a_r][k0 + a_c]);
            ldsm_x4_t(bfr, &kk[ne + b_r][k0 + b_c]);
            mma_bf16(acc[0], afr[0], afr[1], afr[2], afr[3], bfr[0], bfr[1]);
            mma_bf16(acc[1], afr[0], afr[1], afr[2], afr[3], bfr[2], bfr[3]);
        }
        #pragma unroll
        for (int j = 0; j < 2; j++)
            #pragma unroll
            for (int h = 0; h < 2; h++) {
                es[me + g + 8 * h][ne + 8 * j + 2 * c] = acc[j][2 * h];
                es[me + g + 8 * h][ne + 8 * j + 2 * c + 1] = acc[j][2 * h + 1];
            }
    }
    __syncthreads();

    #pragma unroll
    for (int r = 0; r < 8; r++) {
        int i = w * 8 + r;
        float v = es[i][lane];
        float mx = v;
        #pragma unroll
        for (int off = 16; off > 0; off >>= 1)
            mx = fmaxf(mx, __shfl_xor_sync(0xffffffffu, mx, off));
        float ex = __expf(v - mx);
        float sm = ex;
        #pragma unroll
        for (int off = 16; off > 0; off >>= 1)
            sm += __shfl_xor_sync(0xffffffffu, sm, off);
        float dj = (float)(lane - i);
        as_[i][lane] = __float2bfloat16_rn(
            ex / (sm * SCALE_F) * __expf(-dj * dj * (1.0f / 16.0f)));
    }
    __syncthreads();

    {
        int mv = 16 * (w & 1), nv0 = (w >> 1) * 64;
        float oacc[8][4] = {};
        #pragma unroll
        for (int k0 = 0; k0 < 32; k0 += 16) {
            uint32_t afr[4];
            ldsm_x4(afr, &as_[mv + a_r][k0 + a_c]);
            #pragma unroll
            for (int jj = 0; jj < 4; jj++) {
                uint32_t bfr[4];
                ldsm_x4_t(bfr, &vv[k0 + b_r][nv0 + 16 * jj + b_c]);
                mma_bf16(oacc[2 * jj], afr[0], afr[1], afr[2], afr[3], bfr[0], bfr[1]);
                mma_bf16(oacc[2 * jj + 1], afr[0], afr[1], afr[2], afr[3], bfr[2], bfr[3]);
            }
        }
        #pragma unroll
        for (int j = 0; j < 8; j++)
            #pragma unroll
            for (int h = 0; h < 2; h++) {
                int tok = mv + g + 8 * h;
                int col = nv0 + 8 * j + 2 * c;
                *(__nv_bfloat162*)&out[((size_t)(tok * XYH + xy)) * EMBD + col] =
                    cvt2(oacc[j][2 * h], oacc[j][2 * h + 1]);
            }
    }
}

// ---------------- host ---------------------------------------------------------
extern "C" void kernel_launch(void* const* d_in, const int* in_sizes, int n_in,
                              void* d_out, int out_size) {
    (void)in_sizes; (void)n_in; (void)out_size;
    const float* img  = (const float*)d_in[0];
    const float* ln1g = (const float*)d_in[1];
    const float* ln1b = (const float*)d_in[2];
    const float* Wqkv = (const float*)d_in[3];
    const float* bqkv = (const float*)d_in[4];
    const float* Wp   = (const float*)d_in[5];
    const float* bp   = (const float*)d_in[6];
    const float* ln2g = (const float*)d_in[7];
    const float* ln2b = (const float*)d_in[8];
    const float* W1   = (const float*)d_in[9];
    const float* b1   = (const float*)d_in[10];
    const float* W2   = (const float*)d_in[11];
    const float* b2   = (const float*)d_in[12];
    float* out = (float*)d_out;

    float *px, *pbp;
    __nv_bfloat16 *pqkv, *patt, *pwqkv, *pwpb, *pw1b, *pw2b;
    cudaGetSymbolAddress((void**)&px, g_x);
    cudaGetSymbolAddress((void**)&pqkv, g_qkv);
    cudaGetSymbolAddress((void**)&patt, g_att);
    cudaGetSymbolAddress((void**)&pwqkv, g_wqkv_b);
    cudaGetSymbolAddress((void**)&pwpb, g_wp_b);
    cudaGetSymbolAddress((void**)&pw1b, g_w1_b);
    cudaGetSymbolAddress((void**)&pw2b, g_w2_b);
    cudaGetSymbolAddress((void**)&pbp, g_bp);

    cudaFuncSetAttribute(
        gemm_kernel<128, 384, true, false, false, false, true, false, true>,
        cudaFuncAttributeMaxDynamicSharedMemorySize, GSMEM);
    cudaFuncSetAttribute(
        gemm_kernel<128, 128, false, false, true, true, false, true, false>,
        cudaFuncAttributeMaxDynamicSharedMemorySize, GSMEM);
    cudaFuncSetAttribute(ffn_kernel<false>,
                         cudaFuncAttributeMaxDynamicSharedMemorySize, FSMEM);
    cudaFuncSetAttribute(ffn_kernel<true>,
                         cudaFuncAttributeMaxDynamicSharedMemorySize, FSMEM);

    dim3 tb(32, 8);
    t_in_kernel<<<dim3(NTOK / 32, EMBD / 32), tb>>>(img, px);
    prep_w_kernel<<<2304, 256>>>(Wqkv, bqkv, Wp, W1, W2);

    // first norm1 stats (only explicit reduction pass)
    reduce_kernel<<<NB_RED, 128>>>(px);
    fold_kernel<NB_RED><<<16, 256>>>();
    finalize16<<<1, 256>>>(ln1g, ln1b);

    for (int i = 0; i < 3; i++) {
        if (i > 0) {  // norm1 stats come fused from previous ffn (2048 partials)
            fold_kernel<2048><<<16, 256>>>();
            finalize16<<<1, 256>>>(ln1g + i * EMBD, ln1b + i * EMBD);
        }
        // qkv (norm fused, bf16 out head-major, permuted planes; 3 N-tiles)
        gemm_kernel<128, 384, true, false, false, false, true, false, true>
            <<<dim3(1, NTOK / 128), 256, GSMEM>>>(px, pwqkv + (size_t)i * 49152,
                                                  pbp + i * 384, pqkv);
        // attention (tensor-core, contiguous per-head qkv)
        attn_kernel<<<XYH, 128>>>(pqkv, patt);
        // proj (bf16 A) + residual + fused norm2 stats (1024 partials)
        gemm_kernel<128, 128, false, false, true, true, false, true, false>
            <<<dim3(1, NTOK / 128), 256, GSMEM>>>(patt, pwpb + (size_t)i * 16384,
                                                  bp + i * EMBD, px);
        fold_kernel<1024><<<16, 256>>>();
        finalize16<<<1, 256>>>(ln2g + i * EMBD, ln2b + i * EMBD);
        // fused FFN (norm fused, M=64, 2 CTAs/SM) + residual
        if (i < 2) {
            ffn_kernel<false><<<dim3(1, NTOK / 64), 256, FSMEM>>>(
                px, pw1b + (size_t)i * 65536, b1 + i * HID,
                pw2b + (size_t)i * 65536, b2 + i * EMBD, px, nullptr);
        } else {
            // last layer: fused relu + transpose directly into out
            ffn_kernel<true><<<dim3(1, NTOK / 64), 256, FSMEM>>>(
                px, pw1b + (size_t)i * 65536, b1 + i * HID,
                pw2b + (size_t)i * 65536, b2 + i * EMBD, px, out);
        }
    }
}

// round 16
// speedup vs baseline: 1.2793x; 1.2793x over previous
#include <cuda_runtime.h>
#include <cuda_bf16.h>
#include <math.h>
#include <stdint.h>

#define NTOK 131072
#define EMBD 128
#define XYH  4096
#define HID  512
#define NB_RED 256
#define ROWS_PER_RED (NTOK / NB_RED)   // 512
#define SCALE_F 11.313708498984761f    // sqrt(128)
#define GSMEM (3 * 128 * 136 * 2 + 2 * 256 * 4)       // proj: As+Bs0+Bs1+stats = 106496
#define FSMEM (4 * 128 * 136 * 2 + 2 * 256 * 4)       // ffn: As+B0+B1+Hs+stats = 141312
#define QASMEM (6 * 128 * 136 * 2)                    // fused qkv+attn = 208896

// ---------------- scratch (device globals; no allocation allowed) ------------
__device__ float g_x[NTOK * EMBD];              // residual stream [N, E] fp32
__device__ __nv_bfloat16 g_att[NTOK * EMBD];    // attention output, bf16 [N, E]
__device__ float g_part[1024 * 256];            // per-CTA partial sums / sumsq
__device__ float g_part2[16 * 256];             // stage-2 partials
__device__ float g_scale[EMBD];                 // folded norm scale per channel
__device__ float g_shift[EMBD];                 // folded norm shift per channel
// pre-converted bf16 weights
__device__ __nv_bfloat16 g_wqkv_b[3 * 128 * 384];   // permuted [q|k|v] planes
__device__ __nv_bfloat16 g_wp_b[3 * 128 * 128];
__device__ __nv_bfloat16 g_w1_b[3 * 128 * 512];
__device__ __nv_bfloat16 g_w2_b[3 * 512 * 128];
__device__ float g_bp[3 * 384];                 // permuted bqkv (fp32)

// ---------------- PTX helpers --------------------------------------------------
__device__ __forceinline__ void mma_bf16(float* d, uint32_t a0, uint32_t a1,
                                         uint32_t a2, uint32_t a3,
                                         uint32_t b0, uint32_t b1) {
    asm volatile(
        "mma.sync.aligned.m16n8k16.row.col.f32.bf16.bf16.f32 "
        "{%0,%1,%2,%3}, {%4,%5,%6,%7}, {%8,%9}, {%0,%1,%2,%3};\n"
        : "+f"(d[0]), "+f"(d[1]), "+f"(d[2]), "+f"(d[3])
        : "r"(a0), "r"(a1), "r"(a2), "r"(a3), "r"(b0), "r"(b1));
}

__device__ __forceinline__ void ldsm_x4(uint32_t* r, const void* p) {
    uint32_t addr = (uint32_t)__cvta_generic_to_shared(p);
    asm volatile("ldmatrix.sync.aligned.m8n8.x4.shared.b16 {%0,%1,%2,%3}, [%4];"
                 : "=r"(r[0]), "=r"(r[1]), "=r"(r[2]), "=r"(r[3]) : "r"(addr));
}

__device__ __forceinline__ void ldsm_x4_t(uint32_t* r, const void* p) {
    uint32_t addr = (uint32_t)__cvta_generic_to_shared(p);
    asm volatile("ldmatrix.sync.aligned.m8n8.x4.trans.shared.b16 {%0,%1,%2,%3}, [%4];"
                 : "=r"(r[0]), "=r"(r[1]), "=r"(r[2]), "=r"(r[3]) : "r"(addr));
}

__device__ __forceinline__ void cp16(void* smem, const void* gmem) {
    uint32_t s = (uint32_t)__cvta_generic_to_shared(smem);
    asm volatile("cp.async.ca.shared.global [%0], [%1], 16;" :: "r"(s), "l"(gmem));
}

__device__ __forceinline__ void cp_commit() {
    asm volatile("cp.async.commit_group;" ::: "memory");
}

__device__ __forceinline__ void cp_wait0() {
    asm volatile("cp.async.wait_group 0;" ::: "memory");
}

__device__ __forceinline__ void cp_wait_all() {
    asm volatile("cp.async.commit_group;\ncp.async.wait_group 0;" ::: "memory");
}

__device__ __forceinline__ __nv_bfloat162 cvt2(float x, float y) {
    return __nv_bfloat162(__float2bfloat16_rn(x), __float2bfloat16_rn(y));
}

// ---------------- transpose in: img [E, N] -> x [N, E] -----------------------
__global__ void t_in_kernel(const float* __restrict__ img, float* __restrict__ x) {
    __shared__ float tile[32][33];
    int n0 = blockIdx.x * 32, m0 = blockIdx.y * 32;
    #pragma unroll
    for (int r = threadIdx.y; r < 32; r += 8)
        tile[r][threadIdx.x] = img[(size_t)(m0 + r) * NTOK + n0 + threadIdx.x];
    __syncthreads();
    #pragma unroll
    for (int r = threadIdx.y; r < 32; r += 8)
        x[(size_t)(n0 + r) * EMBD + m0 + threadIdx.x] = tile[threadIdx.x][r];
}

// ---------------- one-time weight prep: permute Wqkv, cvt all weights bf16 ----
__global__ void prep_w_kernel(const float* __restrict__ Wqkv, const float* __restrict__ bqkv,
                              const float* __restrict__ Wp, const float* __restrict__ W1,
                              const float* __restrict__ W2) {
    int idx = blockIdx.x * 256 + threadIdx.x;
    if (idx < 147456) {
        int l = idx / 49152, rem = idx % 49152;
        int k = rem / 384, cc = rem % 384;
        g_wqkv_b[l * 49152 + k * 384 + (cc % 3) * 128 + cc / 3] =
            __float2bfloat16_rn(Wqkv[idx]);
    } else if (idx < 196608) {
        int j = idx - 147456;
        g_wp_b[j] = __float2bfloat16_rn(Wp[j]);
    } else if (idx < 393216) {
        int j = idx - 196608;
        g_w1_b[j] = __float2bfloat16_rn(W1[j]);
    } else if (idx < 589824) {
        int j = idx - 393216;
        g_w2_b[j] = __float2bfloat16_rn(W2[j]);
    }
    if (idx < 3 * 384) {
        int l = idx / 384, cc = idx % 384;
        g_bp[l * 384 + (cc % 3) * 128 + cc / 3] = bqkv[idx];
    }
}

// ---------------- instance norm: stage 1 (only for the very first norm) -------
__global__ void reduce_kernel(const float* __restrict__ x) {
    int b = blockIdx.x;
    int c = threadIdx.x;
    float s = 0.f, ss = 0.f;
    int r0 = b * ROWS_PER_RED;
    for (int r = 0; r < ROWS_PER_RED; r++) {
        float v = x[(size_t)(r0 + r) * EMBD + c];
        s += v;
        ss += v * v;
    }
    g_part[b * 256 + c] = s;
    g_part[b * 256 + 128 + c] = ss;
}

// ---------------- norm fold stage A: NP partials -> 16 partials ---------------
template <int NP>
__global__ void fold_kernel() {
    int b = blockIdx.x;        // 16
    int c = threadIdx.x;       // 256
    const int SEG = NP / 16;
    float s = 0.f;
    for (int r = 0; r < SEG; r++) s += g_part[(size_t)(b * SEG + r) * 256 + c];
    g_part2[b * 256 + c] = s;
}

// ---------------- norm fold stage B: 16 partials -> scale/shift ---------------
__global__ void finalize16(const float* __restrict__ g, const float* __restrict__ b) {
    __shared__ float sh[256];
    int t = threadIdx.x;       // 256
    float s = 0.f;
    #pragma unroll
    for (int r = 0; r < 16; r++) s += g_part2[r * 256 + t];
    sh[t] = s;
    __syncthreads();
    if (t < 128) {
        float su = sh[t], ss = sh[t + 128];
        float mean = su * (1.0f / NTOK);
        float var = ss * (1.0f / NTOK) - mean * mean;
        float sc = rsqrtf(var + 1e-5f) * g[t];
        g_scale[t] = sc;
        g_shift[t] = b[t] - mean * sc;
    }
}

// ---------------- FUSED qkv GEMM + attention -----------------------------------
// CTA = 4 heads (xy0..xy0+3) x 32 z = 128 head-major rows.
// Phase 1: normed A (gathered) x permuted Wqkv -> Q/K/V tiles in SMEM (3 N-tiles).
// Phase 2: per-head QK^T, softmax(+gaussian,/SCALE), PV -> att [N,E] bf16.
__global__ __launch_bounds__(256, 1) void qkv_attn_kernel(
        const float* __restrict__ px,
        const __nv_bfloat16* __restrict__ W,     // [128][384] permuted planes
        const float* __restrict__ bias,          // [384] permuted
        __nv_bfloat16* __restrict__ att) {
    extern __shared__ char sm_raw[];
    typedef __nv_bfloat16 bfrow[136];
    bfrow* As  = (bfrow*)sm_raw;
    bfrow* Bs0 = (bfrow*)(sm_raw + 34816);
    bfrow* Bs1 = (bfrow*)(sm_raw + 2 * 34816);
    bfrow* Qs  = (bfrow*)(sm_raw + 3 * 34816);
    bfrow* Ks  = (bfrow*)(sm_raw + 4 * 34816);
    bfrow* Vs  = (bfrow*)(sm_raw + 5 * 34816);
    // attention-phase scratch reuses the As region (GEMM done by then)
    float (*es)[33] = (float(*)[33])sm_raw;              // [128][33] = 16896 B
    typedef __nv_bfloat16 bfrow40[40];
    bfrow40* as_ = (bfrow40*)(sm_raw + 16896);           // [128][40] = 10240 B

    int tid = threadIdx.x;
    int xy0 = blockIdx.y * 4;
    int lane = tid & 31, wid = tid >> 5;
    int wm0 = (wid & 1) * 64;
    int wn0 = (wid >> 1) * 32;
    int g = lane >> 2, c = lane & 3;

    int a_r = lane & 15, a_c = (lane >> 4) * 8;
    int b_r = (lane & 7) + ((lane >> 3) & 1) * 8, b_c = (lane >> 4) * 8;
    int cprow = tid >> 4, cpcol = (tid & 15) * 8;

    // prefetch B tile 0 (q plane)
    #pragma unroll
    for (int r = 0; r < 8; r++) {
        int rr = cprow + 16 * r;
        cp16(&Bs0[rr][cpcol], &W[(size_t)rr * 384 + cpcol]);
    }
    cp_commit();

    // ---- A load: head-major gather, fp32 + norm -> bf16
    {
        int row0 = tid >> 3, colb = (tid & 7) * 4;
        #pragma unroll
        for (int r = 0; r < 4; r++) {
            int rr = row0 + 32 * r;                        // local row = h*32+z
            size_t gtok = (size_t)(rr & 31) * XYH + xy0 + (rr >> 5);
            #pragma unroll
            for (int cb = 0; cb < 4; cb++) {
                int col = colb + 32 * cb;
                float4 v = *(const float4*)&px[gtok * 128 + col];
                float4 sc = *(const float4*)&g_scale[col];
                float4 sh = *(const float4*)&g_shift[col];
                v.x = fmaf(v.x, sc.x, sh.x);
                v.y = fmaf(v.y, sc.y, sh.y);
                v.z = fmaf(v.z, sc.z, sh.z);
                v.w = fmaf(v.w, sc.w, sh.w);
                *(__nv_bfloat162*)&As[rr][col] = cvt2(v.x, v.y);
                *(__nv_bfloat162*)&As[rr][col + 2] = cvt2(v.z, v.w);
            }
        }
    }

    // ---- Phase 1: 3 N-tiles -> Qs / Ks / Vs
    #pragma unroll
    for (int nt = 0; nt < 3; nt++) {
        cp_wait0();
        __syncthreads();
        bfrow* Bc = (nt & 1) ? Bs1 : Bs0;
        if (nt + 1 < 3) {
            bfrow* Bn = (nt & 1) ? Bs0 : Bs1;
            #pragma unroll
            for (int r = 0; r < 8; r++) {
                int rr = cprow + 16 * r;
                cp16(&Bn[rr][cpcol], &W[(size_t)rr * 384 + (nt + 1) * 128 + cpcol]);
            }
            cp_commit();
        }

        float acc[4][4][4] = {};
        #pragma unroll
        for (int ks = 0; ks < 128; ks += 16) {
            uint32_t bfr[2][4];
            ldsm_x4_t(bfr[0], &Bc[ks + b_r][wn0 + b_c]);
            ldsm_x4_t(bfr[1], &Bc[ks + b_r][wn0 + 16 + b_c]);
            #pragma unroll
            for (int i = 0; i < 4; i++) {
                uint32_t afr[4];
                ldsm_x4(afr, &As[wm0 + 16 * i + a_r][ks + a_c]);
                #pragma unroll
                for (int j = 0; j < 4; j++)
                    mma_bf16(acc[i][j], afr[0], afr[1], afr[2], afr[3],
                             bfr[j >> 1][(j & 1) * 2], bfr[j >> 1][(j & 1) * 2 + 1]);
            }
        }
        bfrow* dst = (nt == 0) ? Qs : ((nt == 1) ? Ks : Vs);
        #pragma unroll
        for (int i = 0; i < 4; i++) {
            #pragma unroll
            for (int h = 0; h < 2; h++) {
                int row = wm0 + 16 * i + g + 8 * h;
                #pragma unroll
                for (int j = 0; j < 4; j++) {
                    int col = wn0 + 8 * j + 2 * c;
                    float2 bv = *(const float2*)&bias[nt * 128 + col];
                    *(__nv_bfloat162*)&dst[row][col] =
                        cvt2(acc[i][j][2 * h] + bv.x, acc[i][j][2 * h + 1] + bv.y);
                }
            }
        }
    }
    __syncthreads();   // Q/K/V complete; As region free for reuse

    // ---- Phase 2a: energy; warp w -> head (w>>1), m-strip (w&1)*16
    {
        int h = wid >> 1, me = (wid & 1) * 16;
        float acc[2][2][4] = {};
        #pragma unroll
        for (int k0 = 0; k0 < 128; k0 += 16) {
            uint32_t afr[4];
            ldsm_x4(afr, &Qs[h * 32 + me + a_r][k0 + a_c]);
            #pragma unroll
            for (int ne2 = 0; ne2 < 2; ne2++) {
                uint32_t bfr[4];
                ldsm_x4_t(bfr, &Ks[h * 32 + ne2 * 16 + b_r][k0 + b_c]);
                mma_bf16(acc[ne2][0], afr[0], afr[1], afr[2], afr[3], bfr[0], bfr[1]);
                mma_bf16(acc[ne2][1], afr[0], afr[1], afr[2], afr[3], bfr[2], bfr[3]);
            }
        }
        #pragma unroll
        for (int ne2 = 0; ne2 < 2; ne2++)
            #pragma unroll
            for (int j = 0; j < 2; j++)
                #pragma unroll
                for (int hh = 0; hh < 2; hh++) {
                    int ri = h * 32 + me + g + 8 * hh;
                    int cj = ne2 * 16 + 8 * j + 2 * c;
                    es[ri][cj]     = acc[ne2][j][2 * hh];
                    es[ri][cj + 1] = acc[ne2][j][2 * hh + 1];
                }
    }
    __syncthreads();

    // ---- Phase 2b: softmax + /SCALE + gaussian; warp w rows w*16..w*16+15
    #pragma unroll
    for (int r = 0; r < 16; r++) {
        int ri = wid * 16 + r;
        int i = ri & 31;
        float v = es[ri][lane];
        float mx = v;
        #pragma unroll
        for (int off = 16; off > 0; off >>= 1)
            mx = fmaxf(mx, __shfl_xor_sync(0xffffffffu, mx, off));
        float ex = __expf(v - mx);
        float sm = ex;
        #pragma unroll
        for (int off = 16; off > 0; off >>= 1)
            sm += __shfl_xor_sync(0xffffffffu, sm, off);
        float dj = (float)(lane - i);
        as_[ri][lane] = __float2bfloat16_rn(
            ex / (sm * SCALE_F) * __expf(-dj * dj * (1.0f / 16.0f)));
    }
    __syncthreads();

    // ---- Phase 2c: O = att V; warp w -> head (w>>1), m-strip (w&1)*16, n128
    {
        int h = wid >> 1, mv = (wid & 1) * 16;
        float oacc[16][4] = {};
        #pragma unroll
        for (int k0 = 0; k0 < 32; k0 += 16) {
            uint32_t afr[4];
            ldsm_x4(afr, &as_[h * 32 + mv + a_r][k0 + a_c]);
            #pragma unroll
            for (int jj = 0; jj < 8; jj++) {
                uint32_t bfr[4];
                ldsm_x4_t(bfr, &Vs[h * 32 + k0 + b_r][16 * jj + b_c]);
                mma_bf16(oacc[2 * jj], afr[0], afr[1], afr[2], afr[3], bfr[0], bfr[1]);
                mma_bf16(oacc[2 * jj + 1], afr[0], afr[1], afr[2], afr[3], bfr[2], bfr[3]);
            }
        }
        #pragma unroll
        for (int j = 0; j < 16; j++)
            #pragma unroll
            for (int hh = 0; hh < 2; hh++) {
                int z = mv + g + 8 * hh;
                size_t gtok = (size_t)z * XYH + xy0 + h;
                int col = 8 * j + 2 * c;
                *(__nv_bfloat162*)&att[gtok * 128 + col] =
                    cvt2(oacc[j][2 * hh], oacc[j][2 * hh + 1]);
            }
    }
}

// ---------------- bf16 tensor-core GEMM (proj) ---------------------------------
template <int K, int NC, bool NORM, bool HSWISH, bool RES, bool ABF16, bool OBF16, bool STATS>
__global__ __launch_bounds__(256, 2) void gemm_kernel(const void* __restrict__ Av,
                                                      const __nv_bfloat16* __restrict__ W,
                                                      const float* __restrict__ bias,
                                                      void* __restrict__ Cv) {
    constexpr int NT = NC / 128;
    static_assert(K == 128, "K=128 only");

    extern __shared__ char sm_raw[];
    typedef __nv_bfloat16 bfrow[136];
    bfrow* As  = (bfrow*)sm_raw;
    bfrow* Bs0 = (bfrow*)(sm_raw + 34816);
    bfrow* Bs1 = (bfrow*)(sm_raw + 2 * 34816);
    float* s_sum = (float*)(sm_raw + 3 * 34816);
    float* s_ss  = s_sum + 256;

    int tid = threadIdx.x;
    int m0 = blockIdx.y * 128;
    int lane = tid & 31, wid = tid >> 5;
    int wm0 = (wid & 1) * 64;
    int wn0 = (wid >> 1) * 32;
    int g = lane >> 2, c = lane & 3;

    float csum[8] = {}, css[8] = {};

    int a_r = lane & 15, a_c = (lane >> 4) * 8;
    int b_r = (lane & 7) + ((lane >> 3) & 1) * 8, b_c = (lane >> 4) * 8;
    int cprow = tid >> 4, cpcol = (tid & 15) * 8;

    #pragma unroll
    for (int r = 0; r < 8; r++) {
        int rr = cprow + 16 * r;
        cp16(&Bs0[rr][cpcol], &W[(size_t)rr * NC + cpcol]);
    }
    cp_commit();

    if (ABF16) {
        const __nv_bfloat16* A = (const __nv_bfloat16*)Av;
        #pragma unroll
        for (int r = 0; r < 8; r++) {
            int rr = cprow + 16 * r;
            cp16(&As[rr][cpcol], &A[(size_t)(m0 + rr) * 128 + cpcol]);
        }
        cp_commit();
    } else {
        const float* A = (const float*)Av;
        int row0 = tid >> 3, colb = (tid & 7) * 4;
        #pragma unroll
        for (int r = 0; r < 4; r++) {
            int rr = row0 + 32 * r;
            #pragma unroll
            for (int cb = 0; cb < 4; cb++) {
                int col = colb + 32 * cb;
                float4 v = *(const float4*)&A[(size_t)(m0 + rr) * 128 + col];
                if (NORM) {
                    float4 sc = *(const float4*)&g_scale[col];
                    float4 sh = *(const float4*)&g_shift[col];
                    v.x = fmaf(v.x, sc.x, sh.x);
                    v.y = fmaf(v.y, sc.y, sh.y);
                    v.z = fmaf(v.z, sc.z, sh.z);
                    v.w = fmaf(v.w, sc.w, sh.w);
                }
                *(__nv_bfloat162*)&As[rr][col] = cvt2(v.x, v.y);
                *(__nv_bfloat162*)&As[rr][col + 2] = cvt2(v.z, v.w);
            }
        }
    }

    #pragma unroll
    for (int nt = 0; nt < NT; nt++) {
        cp_wait0();
        __syncthreads();
        bfrow* Bc = (nt & 1) ? Bs1 : Bs0;
        if (nt + 1 < NT) {
            bfrow* Bn = (nt & 1) ? Bs0 : Bs1;
            #pragma unroll
            for (int r = 0; r < 8; r++) {
                int rr = cprow + 16 * r;
                cp16(&Bn[rr][cpcol], &W[(size_t)rr * NC + (nt + 1) * 128 + cpcol]);
            }
            cp_commit();
        }

        float acc[4][4][4] = {};
        #pragma unroll
        for (int ks = 0; ks < 128; ks += 16) {
            uint32_t bfr[2][4];
            ldsm_x4_t(bfr[0], &Bc[ks + b_r][wn0 + b_c]);
            ldsm_x4_t(bfr[1], &Bc[ks + b_r][wn0 + 16 + b_c]);
            #pragma unroll
            for (int i = 0; i < 4; i++) {
                uint32_t afr[4];
                ldsm_x4(afr, &As[wm0 + 16 * i + a_r][ks + a_c]);
                #pragma unroll
                for (int j = 0; j < 4; j++)
                    mma_bf16(acc[i][j], afr[0], afr[1], afr[2], afr[3],
                             bfr[j >> 1][(j & 1) * 2], bfr[j >> 1][(j & 1) * 2 + 1]);
            }
        }
        #pragma unroll
        for (int i = 0; i < 4; i++) {
            #pragma unroll
            for (int h = 0; h < 2; h++) {
                int row = m0 + wm0 + 16 * i + g + 8 * h;
                #pragma unroll
                for (int j = 0; j < 4; j++) {
                    int col = nt * 128 + wn0 + 8 * j + 2 * c;
                    float2 bv = *(const float2*)&bias[col];
                    float x0 = acc[i][j][2 * h + 0] + bv.x;
                    float x1 = acc[i][j][2 * h + 1] + bv.y;
                    if (HSWISH) {
                        x0 = x0 * fminf(fmaxf(x0 + 3.f, 0.f), 6.f) * (1.f / 6.f);
                        x1 = x1 * fminf(fmaxf(x1 + 3.f, 0.f), 6.f) * (1.f / 6.f);
                    }
                    if (OBF16) {
                        __nv_bfloat16* Cb = (__nv_bfloat16*)Cv;
                        *(__nv_bfloat162*)&Cb[(size_t)row * NC + col] = cvt2(x0, x1);
                    } else {
                        float2* cp = (float2*)&((float*)Cv)[(size_t)row * NC + col];
                        if (RES) {
                            float2 rr = *cp;
                            x0 += rr.x; x1 += rr.y;
                        }
                        *cp = make_float2(x0, x1);
                        if (STATS) {
                            csum[2 * j]     += x0;  css[2 * j]     += x0 * x0;
                            csum[2 * j + 1] += x1;  css[2 * j + 1] += x1 * x1;
                        }
                    }
                }
            }
        }
    }

    if (STATS) {
        #pragma unroll
        for (int k = 0; k < 8; k++) {
            #pragma unroll
            for (int off = 4; off < 32; off <<= 1) {
                csum[k] += __shfl_xor_sync(0xffffffffu, csum[k], off);
                css[k]  += __shfl_xor_sync(0xffffffffu, css[k], off);
            }
        }
        __syncthreads();
        if (lane < 4) {
            #pragma unroll
            for (int j = 0; j < 4; j++) {
                int col = wn0 + 8 * j + 2 * lane;
                s_sum[(wid & 1) * 128 + col]     = csum[2 * j];
                s_sum[(wid & 1) * 128 + col + 1] = csum[2 * j + 1];
                s_ss[(wid & 1) * 128 + col]      = css[2 * j];
                s_ss[(wid & 1) * 128 + col + 1]  = css[2 * j + 1];
            }
        }
        __syncthreads();
        if (tid < 128) {
            g_part[blockIdx.y * 256 + tid]       = s_sum[tid] + s_sum[128 + tid];
            g_part[blockIdx.y * 256 + 128 + tid] = s_ss[tid] + s_ss[128 + tid];
        }
    }
}

// ---------------- fused FFN (256 threads, M=128, proven config) ---------------
template <bool LAST>
__global__ __launch_bounds__(256, 1) void ffn_kernel(const float* __restrict__ px_in,
                                                     const __nv_bfloat16* __restrict__ W1,
                                                     const float* __restrict__ b1,
                                                     const __nv_bfloat16* __restrict__ W2,
                                                     const float* __restrict__ b2,
                                                     float* __restrict__ px_out,
                                                     float* __restrict__ outp) {
    extern __shared__ char sm_raw[];
    typedef __nv_bfloat16 bfrow[136];
    bfrow* As = (bfrow*)sm_raw;
    bfrow* B0 = (bfrow*)(sm_raw + 1 * 34816);
    bfrow* B1 = (bfrow*)(sm_raw + 2 * 34816);
    bfrow* Hs = (bfrow*)(sm_raw + 3 * 34816);
    float* s_sum = (float*)(sm_raw + 4 * 34816);
    float* s_ss  = s_sum + 256;
    float* T = (float*)sm_raw;                  // LAST: [128][132] transpose staging

    int tid = threadIdx.x;
    int m0 = blockIdx.y * 128;
    int lane = tid & 31, wid = tid >> 5;
    int wm0 = (wid & 1) * 64;
    int wn0 = (wid >> 1) * 32;
    int g = lane >> 2, c = lane & 3;

    int a_r = lane & 15, a_c = (lane >> 4) * 8;
    int b_r = (lane & 7) + ((lane >> 3) & 1) * 8, b_c = (lane >> 4) * 8;
    int cprow = tid >> 4, cpcol = (tid & 15) * 8;

    #pragma unroll
    for (int r = 0; r < 8; r++) {
        int rr = cprow + 16 * r;
        cp16(&B0[rr][cpcol], &W1[(size_t)rr * HID + cpcol]);
    }
    cp_commit();

    {
        int row0 = tid >> 3, colb = (tid & 7) * 4;
        #pragma unroll
        for (int r = 0; r < 4; r++) {
            int rr = row0 + 32 * r;
            #pragma unroll
            for (int cb = 0; cb < 4; cb++) {
                int col = colb + 32 * cb;
                float4 v = *(const float4*)&px_in[(size_t)(m0 + rr) * 128 + col];
                float4 sc = *(const float4*)&g_scale[col];
                float4 sh = *(const float4*)&g_shift[col];
                v.x = fmaf(v.x, sc.x, sh.x);
                v.y = fmaf(v.y, sc.y, sh.y);
                v.z = fmaf(v.z, sc.z, sh.z);
                v.w = fmaf(v.w, sc.w, sh.w);
                *(__nv_bfloat162*)&As[rr][col] = cvt2(v.x, v.y);
                *(__nv_bfloat162*)&As[rr][col + 2] = cvt2(v.z, v.w);
            }
        }
    }

    float acc2[4][4][4] = {};

    #pragma unroll
    for (int nt = 0; nt < 4; nt++) {
        cp_wait_all();
        __syncthreads();
        #pragma unroll
        for (int r = 0; r < 8; r++) {
            int rr = cprow + 16 * r;
            cp16(&B1[rr][cpcol], &W2[(size_t)(nt * 128 + rr) * 128 + cpcol]);
        }
        cp_commit();

        float acc1[4][4][4] = {};
        #pragma unroll
        for (int ks = 0; ks < 128; ks += 16) {
            uint32_t bfr[2][4];
            ldsm_x4_t(bfr[0], &B0[ks + b_r][wn0 + b_c]);
            ldsm_x4_t(bfr[1], &B0[ks + b_r][wn0 + 16 + b_c]);
            #pragma unroll
            for (int i = 0; i < 4; i++) {
                uint32_t afr[4];
                ldsm_x4(afr, &As[wm0 + 16 * i + a_r][ks + a_c]);
                #pragma unroll
                for (int j = 0; j < 4; j++)
                    mma_bf16(acc1[i][j], afr[0], afr[1], afr[2], afr[3],
                             bfr[j >> 1][(j & 1) * 2], bfr[j >> 1][(j & 1) * 2 + 1]);
            }
        }
        #pragma unroll
        for (int i = 0; i < 4; i++) {
            #pragma unroll
            for (int h = 0; h < 2; h++) {
                int row = wm0 + 16 * i + g + 8 * h;
                #pragma unroll
                for (int j = 0; j < 4; j++) {
                    int col = wn0 + 8 * j + 2 * c;
                    float2 bv = *(const float2*)&b1[nt * 128 + col];
                    float x0 = acc1[i][j][2 * h + 0] + bv.x;
                    float x1 = acc1[i][j][2 * h + 1] + bv.y;
                    x0 = x0 * fminf(fmaxf(x0 + 3.f, 0.f), 6.f) * (1.f / 6.f);
                    x1 = x1 * fminf(fmaxf(x1 + 3.f, 0.f), 6.f) * (1.f / 6.f);
                    *(__nv_bfloat162*)&Hs[row][col] = cvt2(x0, x1);
                }
            }
        }
        cp_wait_all();
        __syncthreads();

        if (nt < 3) {
            #pragma unroll
            for (int r = 0; r < 8; r++) {
                int rr = cprow + 16 * r;
                cp16(&B0[rr][cpcol], &W1[(size_t)rr * HID + (nt + 1) * 128 + cpcol]);
            }
            cp_commit();
        }

        #pragma unroll
        for (int ks = 0; ks < 128; ks += 16) {
            uint32_t bfr[2][4];
            ldsm_x4_t(bfr[0], &B1[ks + b_r][wn0 + b_c]);
            ldsm_x4_t(bfr[1], &B1[ks + b_r][wn0 + 16 + b_c]);
            #pragma unroll
            for (int i = 0; i < 4; i++) {
                uint32_t afr[4];
                ldsm_x4(afr, &Hs[wm0 + 16 * i + a_r][ks + a_c]);
                #pragma unroll
                for (int j = 0; j < 4; j++)
                    mma_bf16(acc2[i][j], afr[0], afr[1], afr[2], afr[3],
                             bfr[j >> 1][(j & 1) * 2], bfr[j >> 1][(j & 1) * 2 + 1]);
            }
        }
        if (nt < 3) __syncthreads();
    }

    if (!LAST) {
        float csum[8] = {}, css[8] = {};
        #pragma unroll
        for (int i = 0; i < 4; i++) {
            #pragma unroll
            for (int h = 0; h < 2; h++) {
                int row = m0 + wm0 + 16 * i + g + 8 * h;
                #pragma unroll
                for (int j = 0; j < 4; j++) {
                    int col = wn0 + 8 * j + 2 * c;
                    float2 bv = *(const float2*)&b2[col];
                    float2* cp = (float2*)&px_out[(size_t)row * 128 + col];
                    float2 rr = *cp;
                    float x0 = acc2[i][j][2 * h + 0] + bv.x + rr.x;
                    float x1 = acc2[i][j][2 * h + 1] + bv.y + rr.y;
                    *cp = make_float2(x0, x1);
                    csum[2 * j]     += x0;  css[2 * j]     += x0 * x0;
                    csum[2 * j + 1] += x1;  css[2 * j + 1] += x1 * x1;
                }
            }
        }
        #pragma unroll
        for (int k = 0; k < 8; k++) {
            #pragma unroll
            for (int off = 4; off < 32; off <<= 1) {
                csum[k] += __shfl_xor_sync(0xffffffffu, csum[k], off);
                css[k]  += __shfl_xor_sync(0xffffffffu, css[k], off);
            }
        }
        __syncthreads();
        if (lane < 4) {
            #pragma unroll
            for (int j = 0; j < 4; j++) {
                int col = wn0 + 8 * j + 2 * lane;
                s_sum[(wid & 1) * 128 + col]     = csum[2 * j];
                s_sum[(wid & 1) * 128 + col + 1] = csum[2 * j + 1];
                s_ss[(wid & 1) * 128 + col]      = css[2 * j];
                s_ss[(wid & 1) * 128 + col + 1]  = css[2 * j + 1];
            }
        }
        __syncthreads();
        if (tid < 128) {
            g_part[blockIdx.y * 256 + tid]       = s_sum[tid] + s_sum[128 + tid];
            g_part[blockIdx.y * 256 + 128 + tid] = s_ss[tid] + s_ss[128 + tid];
        }
    } else {
        __syncthreads();
        #pragma unroll
        for (int i = 0; i < 4; i++) {
            #pragma unroll
            for (int h = 0; h < 2; h++) {
                int tok = wm0 + 16 * i + g + 8 * h;
                #pragma unroll
                for (int j = 0; j < 4; j++) {
                    int ch = wn0 + 8 * j + 2 * c;
                    float2 bv = *(const float2*)&b2[ch];
                    float2 rr = *(const float2*)&px_in[(size_t)(m0 + tok) * 128 + ch];
                    float x0 = acc2[i][j][2 * h + 0] + bv.x + rr.x;
                    float x1 = acc2[i][j][2 * h + 1] + bv.y + rr.y;
                    T[(ch + 0) * 132 + tok] = fmaxf(x0, 0.f);
                    T[(ch + 1) * 132 + tok] = fmaxf(x1, 0.f);
                }
            }
        }
        __syncthreads();
        int ch = tid >> 1, half = tid & 1;
        const float* Trow = &T[ch * 132 + half * 64];
        float* orow = &outp[(size_t)ch * NTOK + m0 + half * 64];
        #pragma unroll
        for (int q = 0; q < 16; q++)
            *(float4*)&orow[q * 4] = *(const float4*)&Trow[q * 4];
    }
}

// ---------------- host ---------------------------------------------------------
extern "C" void kernel_launch(void* const* d_in, const int* in_sizes, int n_in,
                              void* d_out, int out_size) {
    (void)in_sizes; (void)n_in; (void)out_size;
    const float* img  = (const float*)d_in[0];
    const float* ln1g = (const float*)d_in[1];
    const float* ln1b = (const float*)d_in[2];
    const float* Wqkv = (const float*)d_in[3];
    const float* bqkv = (const float*)d_in[4];
    const float* Wp   = (const float*)d_in[5];
    const float* bp   = (const float*)d_in[6];
    const float* ln2g = (const float*)d_in[7];
    const float* ln2b = (const float*)d_in[8];
    const float* W1   = (const float*)d_in[9];
    const float* b1   = (const float*)d_in[10];
    const float* W2   = (const float*)d_in[11];
    const float* b2   = (const float*)d_in[12];
    float* out = (float*)d_out;

    float *px, *pbp;
    __nv_bfloat16 *patt, *pwqkv, *pwpb, *pw1b, *pw2b;
    cudaGetSymbolAddress((void**)&px, g_x);
    cudaGetSymbolAddress((void**)&patt, g_att);
    cudaGetSymbolAddress((void**)&pwqkv, g_wqkv_b);
    cudaGetSymbolAddress((void**)&pwpb, g_wp_b);
    cudaGetSymbolAddress((void**)&pw1b, g_w1_b);
    cudaGetSymbolAddress((void**)&pw2b, g_w2_b);
    cudaGetSymbolAddress((void**)&pbp, g_bp);

    cudaFuncSetAttribute(qkv_attn_kernel,
                         cudaFuncAttributeMaxDynamicSharedMemorySize, QASMEM);
    cudaFuncSetAttribute(
        gemm_kernel<128, 128, false, false, true, true, false, true>,
        cudaFuncAttributeMaxDynamicSharedMemorySize, GSMEM);
    cudaFuncSetAttribute(ffn_kernel<false>,
                         cudaFuncAttributeMaxDynamicSharedMemorySize, FSMEM);
    cudaFuncSetAttribute(ffn_kernel<true>,
                         cudaFuncAttributeMaxDynamicSharedMemorySize, FSMEM);

    dim3 tb(32, 8);
    t_in_kernel<<<dim3(NTOK / 32, EMBD / 32), tb>>>(img, px);
    prep_w_kernel<<<2304, 256>>>(Wqkv, bqkv, Wp, W1, W2);

    // first norm1 stats
    reduce_kernel<<<NB_RED, 128>>>(px);
    fold_kernel<NB_RED><<<16, 256>>>();
    finalize16<<<1, 256>>>(ln1g, ln1b);

    for (int i = 0; i < 3; i++) {
        if (i > 0) {
            fold_kernel<1024><<<16, 256>>>();
            finalize16<<<1, 256>>>(ln1g + i * EMBD, ln1b + i * EMBD);
        }
        // FUSED qkv GEMM + attention (norm fused, Q/K/V stay in smem)
        qkv_attn_kernel<<<dim3(1, XYH / 4), 256, QASMEM>>>(
            px, pwqkv + (size_t)i * 49152, pbp + i * 384, patt);
        // proj (bf16 A) + residual + fused norm2 stats
        gemm_kernel<128, 128, false, false, true, true, false, true>
            <<<dim3(1, NTOK / 128), 256, GSMEM>>>(patt, pwpb + (size_t)i * 16384,
                                                  bp + i * EMBD, px);
        fold_kernel<1024><<<16, 256>>>();
        finalize16<<<1, 256>>>(ln2g + i * EMBD, ln2b + i * EMBD);
        // fused FFN (norm fused, hidden kept in smem) + residual
        if (i < 2) {
            ffn_kernel<false><<<dim3(1, NTOK / 128), 256, FSMEM>>>(
                px, pw1b + (size_t)i * 65536, b1 + i * HID,
                pw2b + (size_t)i * 65536, b2 + i * EMBD, px, nullptr);
        } else {
            ffn_kernel<true><<<dim3(1, NTOK / 128), 256, FSMEM>>>(
                px, pw1b + (size_t)i * 65536, b1 + i * HID,
                pw2b + (size_t)i * 65536, b2 + i * EMBD, px, out);
        }
    }
}

// round 17
// speedup vs baseline: 1.3708x; 1.0715x over previous
#include <cuda_runtime.h>
#include <cuda_bf16.h>
#include <math.h>
#include <stdint.h>

#define NTOK 131072
#define EMBD 128
#define XYH  4096
#define HID  512
#define NB_RED 256
#define ROWS_PER_RED (NTOK / NB_RED)   // 512
#define SCALE_F 11.313708498984761f    // sqrt(128)
#define FSMEM (4 * 128 * 136 * 2 + 2 * 256 * 4)       // ffn: As+B0+B1+Hs+stats = 141312
#define QASMEM (6 * 128 * 136 * 2 + 2 * 256 * 4)      // fused qkv+attn+proj = 210944

// ---------------- scratch (device globals; no allocation allowed) ------------
__device__ float g_x[NTOK * EMBD];              // residual stream [N, E] fp32
__device__ float g_part[1024 * 256];            // per-CTA partial sums / sumsq
__device__ float g_part2[16 * 256];             // stage-2 partials
__device__ float g_scale[EMBD];                 // folded norm scale per channel
__device__ float g_shift[EMBD];                 // folded norm shift per channel
// pre-converted bf16 weights
__device__ __nv_bfloat16 g_wqkv_b[3 * 128 * 384];   // permuted [q|k|v] planes
__device__ __nv_bfloat16 g_wp_b[3 * 128 * 128];
__device__ __nv_bfloat16 g_w1_b[3 * 128 * 512];
__device__ __nv_bfloat16 g_w2_b[3 * 512 * 128];
__device__ float g_bp[3 * 384];                 // permuted bqkv (fp32)

// ---------------- PTX helpers --------------------------------------------------
__device__ __forceinline__ void mma_bf16(float* d, uint32_t a0, uint32_t a1,
                                         uint32_t a2, uint32_t a3,
                                         uint32_t b0, uint32_t b1) {
    asm volatile(
        "mma.sync.aligned.m16n8k16.row.col.f32.bf16.bf16.f32 "
        "{%0,%1,%2,%3}, {%4,%5,%6,%7}, {%8,%9}, {%0,%1,%2,%3};\n"
        : "+f"(d[0]), "+f"(d[1]), "+f"(d[2]), "+f"(d[3])
        : "r"(a0), "r"(a1), "r"(a2), "r"(a3), "r"(b0), "r"(b1));
}

__device__ __forceinline__ void ldsm_x4(uint32_t* r, const void* p) {
    uint32_t addr = (uint32_t)__cvta_generic_to_shared(p);
    asm volatile("ldmatrix.sync.aligned.m8n8.x4.shared.b16 {%0,%1,%2,%3}, [%4];"
                 : "=r"(r[0]), "=r"(r[1]), "=r"(r[2]), "=r"(r[3]) : "r"(addr));
}

__device__ __forceinline__ void ldsm_x4_t(uint32_t* r, const void* p) {
    uint32_t addr = (uint32_t)__cvta_generic_to_shared(p);
    asm volatile("ldmatrix.sync.aligned.m8n8.x4.trans.shared.b16 {%0,%1,%2,%3}, [%4];"
                 : "=r"(r[0]), "=r"(r[1]), "=r"(r[2]), "=r"(r[3]) : "r"(addr));
}

__device__ __forceinline__ void cp16(void* smem, const void* gmem) {
    uint32_t s = (uint32_t)__cvta_generic_to_shared(smem);
    asm volatile("cp.async.ca.shared.global [%0], [%1], 16;" :: "r"(s), "l"(gmem));
}

__device__ __forceinline__ void cp_commit() {
    asm volatile("cp.async.commit_group;" ::: "memory");
}

__device__ __forceinline__ void cp_wait0() {
    asm volatile("cp.async.wait_group 0;" ::: "memory");
}

__device__ __forceinline__ void cp_wait_all() {
    asm volatile("cp.async.commit_group;\ncp.async.wait_group 0;" ::: "memory");
}

__device__ __forceinline__ __nv_bfloat162 cvt2(float x, float y) {
    return __nv_bfloat162(__float2bfloat16_rn(x), __float2bfloat16_rn(y));
}

// ---------------- transpose in: img [E, N] -> x [N, E] -----------------------
__global__ void t_in_kernel(const float* __restrict__ img, float* __restrict__ x) {
    __shared__ float tile[32][33];
    int n0 = blockIdx.x * 32, m0 = blockIdx.y * 32;
    #pragma unroll
    for (int r = threadIdx.y; r < 32; r += 8)
        tile[r][threadIdx.x] = img[(size_t)(m0 + r) * NTOK + n0 + threadIdx.x];
    __syncthreads();
    #pragma unroll
    for (int r = threadIdx.y; r < 32; r += 8)
        x[(size_t)(n0 + r) * EMBD + m0 + threadIdx.x] = tile[threadIdx.x][r];
}

// ---------------- one-time weight prep: permute Wqkv, cvt all weights bf16 ----
__global__ void prep_w_kernel(const float* __restrict__ Wqkv, const float* __restrict__ bqkv,
                              const float* __restrict__ Wp, const float* __restrict__ W1,
                              const float* __restrict__ W2) {
    int idx = blockIdx.x * 256 + threadIdx.x;
    if (idx < 147456) {
        int l = idx / 49152, rem = idx % 49152;
        int k = rem / 384, cc = rem % 384;
        g_wqkv_b[l * 49152 + k * 384 + (cc % 3) * 128 + cc / 3] =
            __float2bfloat16_rn(Wqkv[idx]);
    } else if (idx < 196608) {
        int j = idx - 147456;
        g_wp_b[j] = __float2bfloat16_rn(Wp[j]);
    } else if (idx < 393216) {
        int j = idx - 196608;
        g_w1_b[j] = __float2bfloat16_rn(W1[j]);
    } else if (idx < 589824) {
        int j = idx - 393216;
        g_w2_b[j] = __float2bfloat16_rn(W2[j]);
    }
    if (idx < 3 * 384) {
        int l = idx / 384, cc = idx % 384;
        g_bp[l * 384 + (cc % 3) * 128 + cc / 3] = bqkv[idx];
    }
}

// ---------------- instance norm: stage 1 (only for the very first norm) -------
__global__ void reduce_kernel(const float* __restrict__ x) {
    int b = blockIdx.x;
    int c = threadIdx.x;
    float s = 0.f, ss = 0.f;
    int r0 = b * ROWS_PER_RED;
    for (int r = 0; r < ROWS_PER_RED; r++) {
        float v = x[(size_t)(r0 + r) * EMBD + c];
        s += v;
        ss += v * v;
    }
    g_part[b * 256 + c] = s;
    g_part[b * 256 + 128 + c] = ss;
}

// ---------------- norm fold stage A: NP partials -> 16 partials ---------------
template <int NP>
__global__ void fold_kernel() {
    int b = blockIdx.x;        // 16
    int c = threadIdx.x;       // 256
    const int SEG = NP / 16;
    float s = 0.f;
    for (int r = 0; r < SEG; r++) s += g_part[(size_t)(b * SEG + r) * 256 + c];
    g_part2[b * 256 + c] = s;
}

// ---------------- norm fold stage B: 16 partials -> scale/shift ---------------
__global__ void finalize16(const float* __restrict__ g, const float* __restrict__ b) {
    __shared__ float sh[256];
    int t = threadIdx.x;       // 256
    float s = 0.f;
    #pragma unroll
    for (int r = 0; r < 16; r++) s += g_part2[r * 256 + t];
    sh[t] = s;
    __syncthreads();
    if (t < 128) {
        float su = sh[t], ss = sh[t + 128];
        float mean = su * (1.0f / NTOK);
        float var = ss * (1.0f / NTOK) - mean * mean;
        float sc = rsqrtf(var + 1e-5f) * g[t];
        g_scale[t] = sc;
        g_shift[t] = b[t] - mean * sc;
    }
}

// ---------------- FUSED qkv GEMM + attention + proj + residual + stats --------
// CTA = 4 heads (xy0..xy0+3) x 32 z = 128 head-major rows.
// Phase 1: normed A (gathered) x permuted Wqkv -> Q/K/V tiles in SMEM (3 N-tiles).
// Phase 2: per-head QK^T, softmax(+gaussian,/SCALE), PV -> O tile in SMEM.
// Phase 3: P = O x Wp + bias_p + residual -> px (scattered rows); norm2 stats.
__global__ __launch_bounds__(256, 1) void qkv_attn_proj_kernel(
        float* __restrict__ px,
        const __nv_bfloat16* __restrict__ W,     // [128][384] permuted planes
        const float* __restrict__ bias,          // [384] permuted bqkv
        const __nv_bfloat16* __restrict__ Wp,    // [128][128]
        const float* __restrict__ bp) {          // [128]
    extern __shared__ char sm_raw[];
    typedef __nv_bfloat16 bfrow[136];
    bfrow* As  = (bfrow*)sm_raw;
    bfrow* Bs0 = (bfrow*)(sm_raw + 34816);
    bfrow* Bs1 = (bfrow*)(sm_raw + 2 * 34816);
    bfrow* Qs  = (bfrow*)(sm_raw + 3 * 34816);
    bfrow* Ks  = (bfrow*)(sm_raw + 4 * 34816);
    bfrow* Vs  = (bfrow*)(sm_raw + 5 * 34816);
    float* s_sum = (float*)(sm_raw + 6 * 34816);
    float* s_ss  = s_sum + 256;
    // attention-phase scratch reuses the As region (GEMM done by then)
    float (*es)[33] = (float(*)[33])sm_raw;              // [128][33] = 16896 B
    typedef __nv_bfloat16 bfrow40[40];
    bfrow40* as_ = (bfrow40*)(sm_raw + 16896);           // [128][40] = 10240 B
    bfrow* Os = Ks;                                      // O tile reuses Ks

    int tid = threadIdx.x;
    int xy0 = blockIdx.y * 4;
    int lane = tid & 31, wid = tid >> 5;
    int wm0 = (wid & 1) * 64;
    int wn0 = (wid >> 1) * 32;
    int g = lane >> 2, c = lane & 3;

    int a_r = lane & 15, a_c = (lane >> 4) * 8;
    int b_r = (lane & 7) + ((lane >> 3) & 1) * 8, b_c = (lane >> 4) * 8;
    int cprow = tid >> 4, cpcol = (tid & 15) * 8;

    // prefetch B tile 0 (q plane)
    #pragma unroll
    for (int r = 0; r < 8; r++) {
        int rr = cprow + 16 * r;
        cp16(&Bs0[rr][cpcol], &W[(size_t)rr * 384 + cpcol]);
    }
    cp_commit();

    // ---- A load: head-major gather, fp32 + norm -> bf16
    {
        int row0 = tid >> 3, colb = (tid & 7) * 4;
        #pragma unroll
        for (int r = 0; r < 4; r++) {
            int rr = row0 + 32 * r;                        // local row = h*32+z
            size_t gtok = (size_t)(rr & 31) * XYH + xy0 + (rr >> 5);
            #pragma unroll
            for (int cb = 0; cb < 4; cb++) {
                int col = colb + 32 * cb;
                float4 v = *(const float4*)&px[gtok * 128 + col];
                float4 sc = *(const float4*)&g_scale[col];
                float4 sh = *(const float4*)&g_shift[col];
                v.x = fmaf(v.x, sc.x, sh.x);
                v.y = fmaf(v.y, sc.y, sh.y);
                v.z = fmaf(v.z, sc.z, sh.z);
                v.w = fmaf(v.w, sc.w, sh.w);
                *(__nv_bfloat162*)&As[rr][col] = cvt2(v.x, v.y);
                *(__nv_bfloat162*)&As[rr][col + 2] = cvt2(v.z, v.w);
            }
        }
    }

    // ---- Phase 1: 3 N-tiles -> Qs / Ks / Vs
    #pragma unroll
    for (int nt = 0; nt < 3; nt++) {
        cp_wait0();
        __syncthreads();
        bfrow* Bc = (nt & 1) ? Bs1 : Bs0;
        if (nt + 1 < 3) {
            bfrow* Bn = (nt & 1) ? Bs0 : Bs1;
            #pragma unroll
            for (int r = 0; r < 8; r++) {
                int rr = cprow + 16 * r;
                cp16(&Bn[rr][cpcol], &W[(size_t)rr * 384 + (nt + 1) * 128 + cpcol]);
            }
            cp_commit();
        }

        float acc[4][4][4] = {};
        #pragma unroll
        for (int ks = 0; ks < 128; ks += 16) {
            uint32_t bfr[2][4];
            ldsm_x4_t(bfr[0], &Bc[ks + b_r][wn0 + b_c]);
            ldsm_x4_t(bfr[1], &Bc[ks + b_r][wn0 + 16 + b_c]);
            #pragma unroll
            for (int i = 0; i < 4; i++) {
                uint32_t afr[4];
                ldsm_x4(afr, &As[wm0 + 16 * i + a_r][ks + a_c]);
                #pragma unroll
                for (int j = 0; j < 4; j++)
                    mma_bf16(acc[i][j], afr[0], afr[1], afr[2], afr[3],
                             bfr[j >> 1][(j & 1) * 2], bfr[j >> 1][(j & 1) * 2 + 1]);
            }
        }
        bfrow* dst = (nt == 0) ? Qs : ((nt == 1) ? Ks : Vs);
        #pragma unroll
        for (int i = 0; i < 4; i++) {
            #pragma unroll
            for (int h = 0; h < 2; h++) {
                int row = wm0 + 16 * i + g + 8 * h;
                #pragma unroll
                for (int j = 0; j < 4; j++) {
                    int col = wn0 + 8 * j + 2 * c;
                    float2 bv = *(const float2*)&bias[nt * 128 + col];
                    *(__nv_bfloat162*)&dst[row][col] =
                        cvt2(acc[i][j][2 * h] + bv.x, acc[i][j][2 * h + 1] + bv.y);
                }
            }
        }
    }
    __syncthreads();   // Q/K/V complete; As, Bs0, Bs1 free

    // prefetch Wp tile into Bs1 (consumed in phase 3; hidden behind phase 2)
    #pragma unroll
    for (int r = 0; r < 8; r++) {
        int rr = cprow + 16 * r;
        cp16(&Bs1[rr][cpcol], &Wp[(size_t)rr * 128 + cpcol]);
    }
    cp_commit();

    // ---- Phase 2a: energy; warp w -> head (w>>1), m-strip (w&1)*16
    {
        int h = wid >> 1, me = (wid & 1) * 16;
        float acc[2][2][4] = {};
        #pragma unroll
        for (int k0 = 0; k0 < 128; k0 += 16) {
            uint32_t afr[4];
            ldsm_x4(afr, &Qs[h * 32 + me + a_r][k0 + a_c]);
            #pragma unroll
            for (int ne2 = 0; ne2 < 2; ne2++) {
                uint32_t bfr[4];
                ldsm_x4_t(bfr, &Ks[h * 32 + ne2 * 16 + b_r][k0 + b_c]);
                mma_bf16(acc[ne2][0], afr[0], afr[1], afr[2], afr[3], bfr[0], bfr[1]);
                mma_bf16(acc[ne2][1], afr[0], afr[1], afr[2], afr[3], bfr[2], bfr[3]);
            }
        }
        #pragma unroll
        for (int ne2 = 0; ne2 < 2; ne2++)
            #pragma unroll
            for (int j = 0; j < 2; j++)
                #pragma unroll
                for (int hh = 0; hh < 2; hh++) {
                    int ri = h * 32 + me + g + 8 * hh;
                    int cj = ne2 * 16 + 8 * j + 2 * c;
                    es[ri][cj]     = acc[ne2][j][2 * hh];
                    es[ri][cj + 1] = acc[ne2][j][2 * hh + 1];
                }
    }
    __syncthreads();

    // ---- Phase 2b: softmax + /SCALE + gaussian; warp w rows w*16..w*16+15
    #pragma unroll
    for (int r = 0; r < 16; r++) {
        int ri = wid * 16 + r;
        int i = ri & 31;
        float v = es[ri][lane];
        float mx = v;
        #pragma unroll
        for (int off = 16; off > 0; off >>= 1)
            mx = fmaxf(mx, __shfl_xor_sync(0xffffffffu, mx, off));
        float ex = __expf(v - mx);
        float sm = ex;
        #pragma unroll
        for (int off = 16; off > 0; off >>= 1)
            sm += __shfl_xor_sync(0xffffffffu, sm, off);
        float dj = (float)(lane - i);
        as_[ri][lane] = __float2bfloat16_rn(
            ex / (sm * SCALE_F) * __expf(-dj * dj * (1.0f / 16.0f)));
    }
    __syncthreads();   // es/as_ ready; Ks reads (2a) done -> Os writable

    // ---- Phase 2c: O = att V -> Os (smem, reuses Ks)
    {
        int h = wid >> 1, mv = (wid & 1) * 16;
        float oacc[16][4] = {};
        #pragma unroll
        for (int k0 = 0; k0 < 32; k0 += 16) {
            uint32_t afr[4];
            ldsm_x4(afr, &as_[h * 32 + mv + a_r][k0 + a_c]);
            #pragma unroll
            for (int jj = 0; jj < 8; jj++) {
                uint32_t bfr[4];
                ldsm_x4_t(bfr, &Vs[h * 32 + k0 + b_r][16 * jj + b_c]);
                mma_bf16(oacc[2 * jj], afr[0], afr[1], afr[2], afr[3], bfr[0], bfr[1]);
                mma_bf16(oacc[2 * jj + 1], afr[0], afr[1], afr[2], afr[3], bfr[2], bfr[3]);
            }
        }
        #pragma unroll
        for (int j = 0; j < 16; j++)
            #pragma unroll
            for (int hh = 0; hh < 2; hh++) {
                int row = h * 32 + mv + g + 8 * hh;
                int col = 8 * j + 2 * c;
                *(__nv_bfloat162*)&Os[row][col] =
                    cvt2(oacc[j][2 * hh], oacc[j][2 * hh + 1]);
            }
    }
    cp_wait0();        // Wp tile ready
    __syncthreads();   // Os visible to all warps

    // ---- Phase 3: P = Os x Wp + bp + residual -> px; norm2 stats
    {
        float acc[4][4][4] = {};
        #pragma unroll
        for (int ks = 0; ks < 128; ks += 16) {
            uint32_t bfr[2][4];
            ldsm_x4_t(bfr[0], &Bs1[ks + b_r][wn0 + b_c]);
            ldsm_x4_t(bfr[1], &Bs1[ks + b_r][wn0 + 16 + b_c]);
            #pragma unroll
            for (int i = 0; i < 4; i++) {
                uint32_t afr[4];
                ldsm_x4(afr, &Os[wm0 + 16 * i + a_r][ks + a_c]);
                #pragma unroll
                for (int j = 0; j < 4; j++)
                    mma_bf16(acc[i][j], afr[0], afr[1], afr[2], afr[3],
                             bfr[j >> 1][(j & 1) * 2], bfr[j >> 1][(j & 1) * 2 + 1]);
            }
        }
        float csum[8] = {}, css[8] = {};
        #pragma unroll
        for (int i = 0; i < 4; i++) {
            #pragma unroll
            for (int h = 0; h < 2; h++) {
                int row = wm0 + 16 * i + g + 8 * h;            // local head-major row
                size_t gtok = (size_t)(row & 31) * XYH + xy0 + (row >> 5);
                #pragma unroll
                for (int j = 0; j < 4; j++) {
                    int col = wn0 + 8 * j + 2 * c;
                    float2 bv = *(const float2*)&bp[col];
                    float2* cp = (float2*)&px[gtok * 128 + col];
                    float2 rr = *cp;
                    float x0 = acc[i][j][2 * h + 0] + bv.x + rr.x;
                    float x1 = acc[i][j][2 * h + 1] + bv.y + rr.y;
                    *cp = make_float2(x0, x1);
                    csum[2 * j]     += x0;  css[2 * j]     += x0 * x0;
                    csum[2 * j + 1] += x1;  css[2 * j + 1] += x1 * x1;
                }
            }
        }
        #pragma unroll
        for (int k = 0; k < 8; k++) {
            #pragma unroll
            for (int off = 4; off < 32; off <<= 1) {
                csum[k] += __shfl_xor_sync(0xffffffffu, csum[k], off);
                css[k]  += __shfl_xor_sync(0xffffffffu, css[k], off);
            }
        }
        __syncthreads();
        if (lane < 4) {
            #pragma unroll
            for (int j = 0; j < 4; j++) {
                int col = wn0 + 8 * j + 2 * lane;
                s_sum[(wid & 1) * 128 + col]     = csum[2 * j];
                s_sum[(wid & 1) * 128 + col + 1] = csum[2 * j + 1];
                s_ss[(wid & 1) * 128 + col]      = css[2 * j];
                s_ss[(wid & 1) * 128 + col + 1]  = css[2 * j + 1];
            }
        }
        __syncthreads();
        if (tid < 128) {
            g_part[blockIdx.y * 256 + tid]       = s_sum[tid] + s_sum[128 + tid];
            g_part[blockIdx.y * 256 + 128 + tid] = s_ss[tid] + s_ss[128 + tid];
        }
    }
}

// ---------------- fused FFN (256 threads, M=128, proven config) ---------------
template <bool LAST>
__global__ __launch_bounds__(256, 1) void ffn_kernel(const float* __restrict__ px_in,
                                                     const __nv_bfloat16* __restrict__ W1,
                                                     const float* __restrict__ b1,
                                                     const __nv_bfloat16* __restrict__ W2,
                                                     const float* __restrict__ b2,
                                                     float* __restrict__ px_out,
                                                     float* __restrict__ outp) {
    extern __shared__ char sm_raw[];
    typedef __nv_bfloat16 bfrow[136];
    bfrow* As = (bfrow*)sm_raw;
    bfrow* B0 = (bfrow*)(sm_raw + 1 * 34816);
    bfrow* B1 = (bfrow*)(sm_raw + 2 * 34816);
    bfrow* Hs = (bfrow*)(sm_raw + 3 * 34816);
    float* s_sum = (float*)(sm_raw + 4 * 34816);
    float* s_ss  = s_sum + 256;
    float* T = (float*)sm_raw;                  // LAST: [128][132] transpose staging

    int tid = threadIdx.x;
    int m0 = blockIdx.y * 128;
    int lane = tid & 31, wid = tid >> 5;
    int wm0 = (wid & 1) * 64;
    int wn0 = (wid >> 1) * 32;
    int g = lane >> 2, c = lane & 3;

    int a_r = lane & 15, a_c = (lane >> 4) * 8;
    int b_r = (lane & 7) + ((lane >> 3) & 1) * 8, b_c = (lane >> 4) * 8;
    int cprow = tid >> 4, cpcol = (tid & 15) * 8;

    #pragma unroll
    for (int r = 0; r < 8; r++) {
        int rr = cprow + 16 * r;
        cp16(&B0[rr][cpcol], &W1[(size_t)rr * HID + cpcol]);
    }
    cp_commit();

    {
        int row0 = tid >> 3, colb = (tid & 7) * 4;
        #pragma unroll
        for (int r = 0; r < 4; r++) {
            int rr = row0 + 32 * r;
            #pragma unroll
            for (int cb = 0; cb < 4; cb++) {
                int col = colb + 32 * cb;
                float4 v = *(const float4*)&px_in[(size_t)(m0 + rr) * 128 + col];
                float4 sc = *(const float4*)&g_scale[col];
                float4 sh = *(const float4*)&g_shift[col];
                v.x = fmaf(v.x, sc.x, sh.x);
                v.y = fmaf(v.y, sc.y, sh.y);
                v.z = fmaf(v.z, sc.z, sh.z);
                v.w = fmaf(v.w, sc.w, sh.w);
                *(__nv_bfloat162*)&As[rr][col] = cvt2(v.x, v.y);
                *(__nv_bfloat162*)&As[rr][col + 2] = cvt2(v.z, v.w);
            }
        }
    }

    float acc2[4][4][4] = {};

    #pragma unroll
    for (int nt = 0; nt < 4; nt++) {
        cp_wait_all();
        __syncthreads();
        #pragma unroll
        for (int r = 0; r < 8; r++) {
            int rr = cprow + 16 * r;
            cp16(&B1[rr][cpcol], &W2[(size_t)(nt * 128 + rr) * 128 + cpcol]);
        }
        cp_commit();

        float acc1[4][4][4] = {};
        #pragma unroll
        for (int ks = 0; ks < 128; ks += 16) {
            uint32_t bfr[2][4];
            ldsm_x4_t(bfr[0], &B0[ks + b_r][wn0 + b_c]);
            ldsm_x4_t(bfr[1], &B0[ks + b_r][wn0 + 16 + b_c]);
            #pragma unroll
            for (int i = 0; i < 4; i++) {
                uint32_t afr[4];
                ldsm_x4(afr, &As[wm0 + 16 * i + a_r][ks + a_c]);
                #pragma unroll
                for (int j = 0; j < 4; j++)
                    mma_bf16(acc1[i][j], afr[0], afr[1], afr[2], afr[3],
                             bfr[j >> 1][(j & 1) * 2], bfr[j >> 1][(j & 1) * 2 + 1]);
            }
        }
        #pragma unroll
        for (int i = 0; i < 4; i++) {
            #pragma unroll
            for (int h = 0; h < 2; h++) {
                int row = wm0 + 16 * i + g + 8 * h;
                #pragma unroll
                for (int j = 0; j < 4; j++) {
                    int col = wn0 + 8 * j + 2 * c;
                    float2 bv = *(const float2*)&b1[nt * 128 + col];
                    float x0 = acc1[i][j][2 * h + 0] + bv.x;
                    float x1 = acc1[i][j][2 * h + 1] + bv.y;
                    x0 = x0 * fminf(fmaxf(x0 + 3.f, 0.f), 6.f) * (1.f / 6.f);
                    x1 = x1 * fminf(fmaxf(x1 + 3.f, 0.f), 6.f) * (1.f / 6.f);
                    *(__nv_bfloat162*)&Hs[row][col] = cvt2(x0, x1);
                }
            }
        }
        cp_wait_all();
        __syncthreads();

        if (nt < 3) {
            #pragma unroll
            for (int r = 0; r < 8; r++) {
                int rr = cprow + 16 * r;
                cp16(&B0[rr][cpcol], &W1[(size_t)rr * HID + (nt + 1) * 128 + cpcol]);
            }
            cp_commit();
        }

        #pragma unroll
        for (int ks = 0; ks < 128; ks += 16) {
            uint32_t bfr[2][4];
            ldsm_x4_t(bfr[0], &B1[ks + b_r][wn0 + b_c]);
            ldsm_x4_t(bfr[1], &B1[ks + b_r][wn0 + 16 + b_c]);
            #pragma unroll
            for (int i = 0; i < 4; i++) {
                uint32_t afr[4];
                ldsm_x4(afr, &Hs[wm0 + 16 * i + a_r][ks + a_c]);
                #pragma unroll
                for (int j = 0; j < 4; j++)
                    mma_bf16(acc2[i][j], afr[0], afr[1], afr[2], afr[3],
                             bfr[j >> 1][(j & 1) * 2], bfr[j >> 1][(j & 1) * 2 + 1]);
            }
        }
        if (nt < 3) __syncthreads();
    }

    if (!LAST) {
        float csum[8] = {}, css[8] = {};
        #pragma unroll
        for (int i = 0; i < 4; i++) {
            #pragma unroll
            for (int h = 0; h < 2; h++) {
                int row = m0 + wm0 + 16 * i + g + 8 * h;
                #pragma unroll
                for (int j = 0; j < 4; j++) {
                    int col = wn0 + 8 * j + 2 * c;
                    float2 bv = *(const float2*)&b2[col];
                    float2* cp = (float2*)&px_out[(size_t)row * 128 + col];
                    float2 rr = *cp;
                    float x0 = acc2[i][j][2 * h + 0] + bv.x + rr.x;
                    float x1 = acc2[i][j][2 * h + 1] + bv.y + rr.y;
                    *cp = make_float2(x0, x1);
                    csum[2 * j]     += x0;  css[2 * j]     += x0 * x0;
                    csum[2 * j + 1] += x1;  css[2 * j + 1] += x1 * x1;
                }
            }
        }
        #pragma unroll
        for (int k = 0; k < 8; k++) {
            #pragma unroll
            for (int off = 4; off < 32; off <<= 1) {
                csum[k] += __shfl_xor_sync(0xffffffffu, csum[k], off);
                css[k]  += __shfl_xor_sync(0xffffffffu, css[k], off);
            }
        }
        __syncthreads();
        if (lane < 4) {
            #pragma unroll
            for (int j = 0; j < 4; j++) {
                int col = wn0 + 8 * j + 2 * lane;
                s_sum[(wid & 1) * 128 + col]     = csum[2 * j];
                s_sum[(wid & 1) * 128 + col + 1] = csum[2 * j + 1];
                s_ss[(wid & 1) * 128 + col]      = css[2 * j];
                s_ss[(wid & 1) * 128 + col + 1]  = css[2 * j + 1];
            }
        }
        __syncthreads();
        if (tid < 128) {
            g_part[blockIdx.y * 256 + tid]       = s_sum[tid] + s_sum[128 + tid];
            g_part[blockIdx.y * 256 + 128 + tid] = s_ss[tid] + s_ss[128 + tid];
        }
    } else {
        __syncthreads();
        #pragma unroll
        for (int i = 0; i < 4; i++) {
            #pragma unroll
            for (int h = 0; h < 2; h++) {
                int tok = wm0 + 16 * i + g + 8 * h;
                #pragma unroll
                for (int j = 0; j < 4; j++) {
                    int ch = wn0 + 8 * j + 2 * c;
                    float2 bv = *(const float2*)&b2[ch];
                    float2 rr = *(const float2*)&px_in[(size_t)(m0 + tok) * 128 + ch];
                    float x0 = acc2[i][j][2 * h + 0] + bv.x + rr.x;
                    float x1 = acc2[i][j][2 * h + 1] + bv.y + rr.y;
                    T[(ch + 0) * 132 + tok] = fmaxf(x0, 0.f);
                    T[(ch + 1) * 132 + tok] = fmaxf(x1, 0.f);
                }
            }
        }
        __syncthreads();
        int ch = tid >> 1, half = tid & 1;
        const float* Trow = &T[ch * 132 + half * 64];
        float* orow = &outp[(size_t)ch * NTOK + m0 + half * 64];
        #pragma unroll
        for (int q = 0; q < 16; q++)
            *(float4*)&orow[q * 4] = *(const float4*)&Trow[q * 4];
    }
}

// ---------------- host ---------------------------------------------------------
extern "C" void kernel_launch(void* const* d_in, const int* in_sizes, int n_in,
                              void* d_out, int out_size) {
    (void)in_sizes; (void)n_in; (void)out_size;
    const float* img  = (const float*)d_in[0];
    const float* ln1g = (const float*)d_in[1];
    const float* ln1b = (const float*)d_in[2];
    const float* Wqkv = (const float*)d_in[3];
    const float* bqkv = (const float*)d_in[4];
    const float* Wp   = (const float*)d_in[5];
    const float* bp   = (const float*)d_in[6];
    const float* ln2g = (const float*)d_in[7];
    const float* ln2b = (const float*)d_in[8];
    const float* W1   = (const float*)d_in[9];
    const float* b1   = (const float*)d_in[10];
    const float* W2   = (const float*)d_in[11];
    const float* b2   = (const float*)d_in[12];
    float* out = (float*)d_out;

    float *px, *pbp;
    __nv_bfloat16 *pwqkv, *pwpb, *pw1b, *pw2b;
    cudaGetSymbolAddress((void**)&px, g_x);
    cudaGetSymbolAddress((void**)&pwqkv, g_wqkv_b);
    cudaGetSymbolAddress((void**)&pwpb, g_wp_b);
    cudaGetSymbolAddress((void**)&pw1b, g_w1_b);
    cudaGetSymbolAddress((void**)&pw2b, g_w2_b);
    cudaGetSymbolAddress((void**)&pbp, g_bp);

    cudaFuncSetAttribute(qkv_attn_proj_kernel,
                         cudaFuncAttributeMaxDynamicSharedMemorySize, QASMEM);
    cudaFuncSetAttribute(ffn_kernel<false>,
                         cudaFuncAttributeMaxDynamicSharedMemorySize, FSMEM);
    cudaFuncSetAttribute(ffn_kernel<true>,
                         cudaFuncAttributeMaxDynamicSharedMemorySize, FSMEM);

    dim3 tb(32, 8);
    t_in_kernel<<<dim3(NTOK / 32, EMBD / 32), tb>>>(img, px);
    prep_w_kernel<<<2304, 256>>>(Wqkv, bqkv, Wp, W1, W2);

    // first norm1 stats
    reduce_kernel<<<NB_RED, 128>>>(px);
    fold_kernel<NB_RED><<<16, 256>>>();
    finalize16<<<1, 256>>>(ln1g, ln1b);

    for (int i = 0; i < 3; i++) {
        if (i > 0) {
            fold_kernel<1024><<<16, 256>>>();
            finalize16<<<1, 256>>>(ln1g + i * EMBD, ln1b + i * EMBD);
        }
        // FUSED qkv GEMM + attention + proj + residual + norm2 stats
        qkv_attn_proj_kernel<<<dim3(1, XYH / 4), 256, QASMEM>>>(
            px, pwqkv + (size_t)i * 49152, pbp + i * 384,
            pwpb + (size_t)i * 16384, bp + i * EMBD);
        fold_kernel<1024><<<16, 256>>>();
        finalize16<<<1, 256>>>(ln2g + i * EMBD, ln2b + i * EMBD);
        // fused FFN (norm fused, hidden kept in smem) + residual
        if (i < 2) {
            ffn_kernel<false><<<dim3(1, NTOK / 128), 256, FSMEM>>>(
                px, pw1b + (size_t)i * 65536, b1 + i * HID,
                pw2b + (size_t)i * 65536, b2 + i * EMBD, px, nullptr);
        } else {
            ffn_kernel<true><<<dim3(1, NTOK / 128), 256, FSMEM>>>(
                px, pw1b + (size_t)i * 65536, b1 + i * HID,
                pw2b + (size_t)i * 65536, b2 + i * EMBD, px, out);
        }
    }
}